// round 1
// baseline (speedup 1.0000x reference)
#include <cuda_runtime.h>
#include <mma.h>
#include <math.h>

using namespace nvcuda;

#define D_MODEL 768
#define NHEAD 12
#define HEAD_DIM 64
#define BATCH 4
#define SEQ 1024
#define MTOT (BATCH*SEQ)
#define NREL 33
#define LDT 72

// scratch (allocation-free requirement -> device globals)
__device__ float g_q[BATCH*NHEAD*SEQ*HEAD_DIM];
__device__ float g_k[BATCH*NHEAD*SEQ*HEAD_DIM];
__device__ float g_v[BATCH*NHEAD*SEQ*HEAD_DIM];
__device__ float g_attn[MTOT*D_MODEL];

// ---------------------------------------------------------------------------
// Generic tf32 GEMM: C[m,n] = sum_k A[m,k] * W[n,k] + bias[n]
// M = 4096 (fixed), K = 768 (fixed), N = gridDim.x*64.
// mode 0: A = x, scatter into g_q/g_k/g_v ([B,H,T,64] layout)
// mode 1: A = g_attn (internal), C -> Cout row-major [4096,768]
// Block tile: 128(M) x 64(N) x 16(K), 256 threads = 8 warps (4x2),
// each warp 32x32 via 2x2 wmma m16n16k8 tf32 fragments.
// ---------------------------------------------------------------------------
__global__ __launch_bounds__(256) void gemm_tf32(
    const float* __restrict__ Ain,
    const float* __restrict__ W,
    const float* __restrict__ bias,
    float* __restrict__ Cout,
    int mode)
{
    __shared__ __align__(128) float sm[128*72];   // 36.9 KB, reused for C
    float* As = sm;              // 128 x 24 (padded)
    float* Bs = sm + 128*24;     // 64 x 24

    const float* A = (mode == 0) ? Ain : g_attn;

    const int n0 = blockIdx.x * 64;
    const int m0 = blockIdx.y * 128;
    const int tid = threadIdx.x;
    const int warp = tid >> 5;
    const int wm = warp >> 1;    // 0..3
    const int wn = warp & 1;     // 0..1

    wmma::fragment<wmma::accumulator,16,16,8,float> c[2][2];
    #pragma unroll
    for (int i = 0; i < 2; i++)
        #pragma unroll
        for (int j = 0; j < 2; j++)
            wmma::fill_fragment(c[i][j], 0.0f);

    for (int kt = 0; kt < 768; kt += 16) {
        // A tile: 128x16 floats = 512 float4, 2 per thread
        #pragma unroll
        for (int u = 0; u < 2; u++) {
            int idx = tid + u*256;
            int r = idx >> 2, c4 = idx & 3;
            *(float4*)&As[r*24 + c4*4] =
                *(const float4*)&A[(size_t)(m0 + r)*768 + kt + c4*4];
        }
        // B tile: 64x16 floats = 256 float4, 1 per thread
        {
            int r = tid >> 2, c4 = tid & 3;
            *(float4*)&Bs[r*24 + c4*4] =
                *(const float4*)&W[(size_t)(n0 + r)*768 + kt + c4*4];
        }
        __syncthreads();

        #pragma unroll
        for (int kk = 0; kk < 16; kk += 8) {
            wmma::fragment<wmma::matrix_a,16,16,8,wmma::precision::tf32,wmma::row_major> a[2];
            wmma::fragment<wmma::matrix_b,16,16,8,wmma::precision::tf32,wmma::col_major> b[2];
            #pragma unroll
            for (int i = 0; i < 2; i++) {
                wmma::load_matrix_sync(a[i], &As[(wm*32 + i*16)*24 + kk], 24);
                #pragma unroll
                for (int e = 0; e < a[i].num_elements; e++)
                    a[i].x[e] = wmma::__float_to_tf32(a[i].x[e]);
            }
            #pragma unroll
            for (int j = 0; j < 2; j++) {
                wmma::load_matrix_sync(b[j], &Bs[(wn*32 + j*16)*24 + kk], 24);
                #pragma unroll
                for (int e = 0; e < b[j].num_elements; e++)
                    b[j].x[e] = wmma::__float_to_tf32(b[j].x[e]);
            }
            #pragma unroll
            for (int i = 0; i < 2; i++)
                #pragma unroll
                for (int j = 0; j < 2; j++)
                    wmma::mma_sync(c[i][j], a[i], b[j], c[i][j]);
        }
        __syncthreads();
    }

    // stage C in smem (reuse), then epilogue
    float* Cs = sm;
    #pragma unroll
    for (int i = 0; i < 2; i++)
        #pragma unroll
        for (int j = 0; j < 2; j++)
            wmma::store_matrix_sync(&Cs[(wm*32 + i*16)*72 + wn*32 + j*16],
                                    c[i][j], 72, wmma::mem_row_major);
    __syncthreads();

    for (int idx = tid; idx < 128*64; idx += 256) {
        int r = idx >> 6, col = idx & 63;
        int m = m0 + r, n = n0 + col;
        float v = Cs[r*72 + col] + bias[n];
        if (mode == 0) {
            int bb = m >> 10, t = m & 1023;
            int c3 = n / 768;
            int rem = n - c3*768;
            int h = rem >> 6, d = rem & 63;
            float* dst = (c3 == 0) ? g_q : (c3 == 1) ? g_k : g_v;
            dst[(size_t)(((bb*NHEAD + h) << 10) + t)*64 + d] = v;
        } else {
            Cout[(size_t)m*768 + n] = v;
        }
    }
}

// ---------------------------------------------------------------------------
// Fused flash attention with relative-position bias.
// grid = (16 q-tiles, 48 bh), 256 threads (8 warps, 4x2 over a 64x64 tile).
// Bias handled via per-block R[t][j] = q_t . rel_pos_emb[j], j in [0,33).
// ---------------------------------------------------------------------------
__global__ __launch_bounds__(256) void attn_flash(const float* __restrict__ rel_emb)
{
    extern __shared__ __align__(128) float smd[];
    float* sQ = smd;              // 64x72 Q tile, reused as PV scratch (Oscr)
    float* sK = smd + 4608;       // 64x72 K tile (holds rel_emb at startup)
    float* sV = smd + 2*4608;     // 64x72 V tile
    float* sS = smd + 3*4608;     // 64x72 scores / probabilities
    float* sO = smd + 4*4608;     // 64x72 output accumulator
    float* sR = smd + 5*4608;     // 64x36 rel projections
    float* sM = sR + 64*36;       // 64 row maxes
    float* sL = sM + 64;          // 64 row sums

    const int t0  = blockIdx.x * 64;
    const int bh  = blockIdx.y;
    const int tid = threadIdx.x;
    const int warp = tid >> 5;
    const int wm = warp >> 1;     // 0..3
    const int wn = warp & 1;      // 0..1
    const int r4 = tid >> 2;      // softmax row (0..63)
    const int q4 = tid & 3;       // quad lane

    const float scale = 0.125f;   // HEAD_DIM^-0.5

    const float* qbase = g_q + (size_t)(bh*SEQ + t0)*64;
    const float* kbase = g_k + (size_t)bh*SEQ*64;
    const float* vbase = g_v + (size_t)bh*SEQ*64;

    // load Q tile + rel emb (into sK region), init O/m/l
    #pragma unroll
    for (int u = 0; u < 4; u++) {
        int idx = tid + u*256;
        int r = idx >> 4, c4 = idx & 15;
        *(float4*)&sQ[r*LDT + c4*4] = *(const float4*)&qbase[r*64 + c4*4];
    }
    for (int idx = tid; idx < NREL*16; idx += 256) {
        int r = idx >> 4, c4 = idx & 15;
        *(float4*)&sK[r*LDT + c4*4] = *(const float4*)&rel_emb[r*64 + c4*4];
    }
    for (int idx = tid; idx < 64*64; idx += 256) {
        int r = idx >> 6, cc = idx & 63;
        sO[r*LDT + cc] = 0.0f;
    }
    if (tid < 64) { sM[tid] = -INFINITY; sL[tid] = 0.0f; }
    __syncthreads();

    // R[r][j] = Q[r] . rel[j]
    for (int idx = tid; idx < 64*NREL; idx += 256) {
        int r = idx / NREL, j = idx - r*NREL;
        float acc = 0.0f;
        #pragma unroll 8
        for (int d = 0; d < 64; d++) acc += sQ[r*LDT + d] * sK[j*LDT + d];
        sR[r*36 + j] = acc;
    }

    // persistent Q fragments (A operand for all 16 S-tiles)
    wmma::fragment<wmma::matrix_a,16,16,8,wmma::precision::tf32,wmma::row_major> qf[8];
    #pragma unroll
    for (int kk = 0; kk < 8; kk++) {
        wmma::load_matrix_sync(qf[kk], &sQ[(wm*16)*LDT + kk*8], LDT);
        #pragma unroll
        for (int e = 0; e < qf[kk].num_elements; e++)
            qf[kk].x[e] = wmma::__float_to_tf32(qf[kk].x[e]);
    }
    __syncthreads();   // sQ/sK free for reuse after this point

    for (int s0 = 0; s0 < SEQ; s0 += 64) {
        // load K,V tiles
        #pragma unroll
        for (int u = 0; u < 4; u++) {
            int idx = tid + u*256;
            int r = idx >> 4, c4 = idx & 15;
            *(float4*)&sK[r*LDT + c4*4] = *(const float4*)&kbase[(size_t)(s0 + r)*64 + c4*4];
            *(float4*)&sV[r*LDT + c4*4] = *(const float4*)&vbase[(size_t)(s0 + r)*64 + c4*4];
        }
        __syncthreads();

        // S = Q @ K^T
        wmma::fragment<wmma::accumulator,16,16,8,float> acc[2];
        wmma::fill_fragment(acc[0], 0.0f);
        wmma::fill_fragment(acc[1], 0.0f);
        #pragma unroll
        for (int kk = 0; kk < 8; kk++) {
            #pragma unroll
            for (int j = 0; j < 2; j++) {
                wmma::fragment<wmma::matrix_b,16,16,8,wmma::precision::tf32,wmma::col_major> bf;
                wmma::load_matrix_sync(bf, &sK[(wn*32 + j*16)*LDT + kk*8], LDT);
                #pragma unroll
                for (int e = 0; e < bf.num_elements; e++)
                    bf.x[e] = wmma::__float_to_tf32(bf.x[e]);
                wmma::mma_sync(acc[j], qf[kk], bf, acc[j]);
            }
        }
        #pragma unroll
        for (int j = 0; j < 2; j++)
            wmma::store_matrix_sync(&sS[(wm*16)*LDT + wn*32 + j*16],
                                    acc[j], LDT, wmma::mem_row_major);
        __syncthreads();

        // online softmax with rel bias (4 threads per row, 16 cols each)
        {
            int r = r4;
            int tg = t0 + r;
            float vals[16];
            float mloc = -INFINITY;
            #pragma unroll
            for (int i = 0; i < 16; i++) {
                int cc = q4*16 + i;
                int dt = (s0 + cc) - tg;
                dt = dt < -16 ? -16 : (dt > 16 ? 16 : dt);
                float v = (sS[r*LDT + cc] + sR[r*36 + dt + 16]) * scale;
                vals[i] = v;
                mloc = fmaxf(mloc, v);
            }
            mloc = fmaxf(mloc, __shfl_xor_sync(0xffffffffu, mloc, 1));
            mloc = fmaxf(mloc, __shfl_xor_sync(0xffffffffu, mloc, 2));
            float m_old = sM[r];
            float m_new = fmaxf(m_old, mloc);
            float lloc = 0.0f;
            #pragma unroll
            for (int i = 0; i < 16; i++) {
                int cc = q4*16 + i;
                float p = __expf(vals[i] - m_new);
                sS[r*LDT + cc] = p;
                lloc += p;
            }
            lloc += __shfl_xor_sync(0xffffffffu, lloc, 1);
            lloc += __shfl_xor_sync(0xffffffffu, lloc, 2);
            float alpha = __expf(m_old - m_new);   // first tile: exp(-inf)=0
            if (q4 == 0) { sM[r] = m_new; sL[r] = sL[r]*alpha + lloc; }
            #pragma unroll
            for (int i = 0; i < 16; i++) {
                int cc = q4*16 + i;
                sO[r*LDT + cc] *= alpha;
            }
        }
        __syncthreads();

        // Oscr(=sQ) = P @ V
        wmma::fill_fragment(acc[0], 0.0f);
        wmma::fill_fragment(acc[1], 0.0f);
        #pragma unroll
        for (int kk = 0; kk < 8; kk++) {
            wmma::fragment<wmma::matrix_a,16,16,8,wmma::precision::tf32,wmma::row_major> pf;
            wmma::load_matrix_sync(pf, &sS[(wm*16)*LDT + kk*8], LDT);
            #pragma unroll
            for (int e = 0; e < pf.num_elements; e++)
                pf.x[e] = wmma::__float_to_tf32(pf.x[e]);
            #pragma unroll
            for (int j = 0; j < 2; j++) {
                wmma::fragment<wmma::matrix_b,16,16,8,wmma::precision::tf32,wmma::row_major> vf;
                wmma::load_matrix_sync(vf, &sV[(kk*8)*LDT + wn*32 + j*16], LDT);
                #pragma unroll
                for (int e = 0; e < vf.num_elements; e++)
                    vf.x[e] = wmma::__float_to_tf32(vf.x[e]);
                wmma::mma_sync(acc[j], pf, vf, acc[j]);
            }
        }
        #pragma unroll
        for (int j = 0; j < 2; j++)
            wmma::store_matrix_sync(&sQ[(wm*16)*LDT + wn*32 + j*16],
                                    acc[j], LDT, wmma::mem_row_major);
        __syncthreads();

        // O += Oscr
        #pragma unroll
        for (int i = 0; i < 16; i++) {
            int cc = q4*16 + i;
            sO[r4*LDT + cc] += sQ[r4*LDT + cc];
        }
        __syncthreads();
    }

    // epilogue: normalize and write [B,T,H*64] layout for the output GEMM
    {
        int bb = bh / NHEAD, h = bh - bb*NHEAD;
        float inv = 1.0f / sL[r4];
        float* out = g_attn + (size_t)(bb*SEQ + t0 + r4)*D_MODEL + h*64;
        #pragma unroll
        for (int i = 0; i < 16; i++) {
            int cc = q4*16 + i;
            out[cc] = sO[r4*LDT + cc] * inv;
        }
    }
}

// ---------------------------------------------------------------------------
extern "C" void kernel_launch(void* const* d_in, const int* in_sizes, int n_in,
                              void* d_out, int out_size)
{
    const float* x     = (const float*)d_in[0];
    const float* qkv_w = (const float*)d_in[1];
    const float* qkv_b = (const float*)d_in[2];
    const float* out_w = (const float*)d_in[3];
    const float* out_b = (const float*)d_in[4];
    const float* rel   = (const float*)d_in[5];
    float* out = (float*)d_out;

    (void)in_sizes; (void)n_in; (void)out_size;

    cudaFuncSetAttribute(attn_flash,
                         cudaFuncAttributeMaxDynamicSharedMemorySize, 102400);

    // 1) QKV projection, scatter to q/k/v [B,H,T,64]
    gemm_tf32<<<dim3(36, 32), 256>>>(x, qkv_w, qkv_b, nullptr, 0);
    // 2) fused attention with relative-position bias
    attn_flash<<<dim3(16, 48), 256, 102400>>>(rel);
    // 3) output projection
    gemm_tf32<<<dim3(12, 32), 256>>>(nullptr, out_w, out_b, out, 1);
}

// round 3
// speedup vs baseline: 1.6777x; 1.6777x over previous
#include <cuda_runtime.h>
#include <mma.h>
#include <math.h>

using namespace nvcuda;

#define D_MODEL 768
#define NHEAD 12
#define HEAD_DIM 64
#define BATCH 4
#define SEQ 1024
#define MTOT (BATCH*SEQ)

// scratch (allocation-free requirement -> device globals)
__device__ float g_q[BATCH*NHEAD*SEQ*HEAD_DIM];
__device__ float g_k[BATCH*NHEAD*SEQ*HEAD_DIM];
__device__ float g_v[BATCH*NHEAD*SEQ*HEAD_DIM];
__device__ float g_attn[MTOT*D_MODEL];

// ---------------------------------------------------------------------------
// helpers
// ---------------------------------------------------------------------------
__device__ __forceinline__ unsigned f2tf(float f) {
    unsigned r;
    asm("cvt.rna.tf32.f32 %0, %1;" : "=r"(r) : "f"(f));
    return r;
}
__device__ __forceinline__ void cp16(void* s, const void* g) {
    unsigned sa = (unsigned)__cvta_generic_to_shared(s);
    asm volatile("cp.async.cg.shared.global [%0], [%1], 16;" :: "r"(sa), "l"(g));
}
#define CP_COMMIT() asm volatile("cp.async.commit_group;")
#define CP_WAIT1()  asm volatile("cp.async.wait_group 1;")
#define CP_WAIT0()  asm volatile("cp.async.wait_group 0;")

__device__ __forceinline__ float ex2(float x) {
    float r;
    asm("ex2.approx.ftz.f32 %0, %1;" : "=f"(r) : "f"(x));
    return r;
}

// mma.m16n8k8 tf32: D += A*B, documented fragment layouts
__device__ __forceinline__ void mma8(float* d, const unsigned* a, unsigned b0, unsigned b1) {
    asm volatile(
        "mma.sync.aligned.m16n8k8.row.col.f32.tf32.tf32.f32 "
        "{%0,%1,%2,%3}, {%4,%5,%6,%7}, {%8,%9}, {%0,%1,%2,%3};"
        : "+f"(d[0]), "+f"(d[1]), "+f"(d[2]), "+f"(d[3])
        : "r"(a[0]), "r"(a[1]), "r"(a[2]), "r"(a[3]), "r"(b0), "r"(b1));
}

// ---------------------------------------------------------------------------
// tf32 GEMM: C[m,n] = sum_k A[m,k] * W[n,k] + bias[n]
// Block 128x128, K-chunk 32, cp.async double-buffered, 256 thr (8 warps 4x2),
// warp tile 32x64 (2x4 wmma 16x16x8). Bias via accumulator init.
// mode 0: A = x, C scattered (tf32-rounded) into g_q/g_k/g_v [B,H,T,64]
// mode 1: A = g_attn, C -> Cout row-major [4096,768]
// ---------------------------------------------------------------------------
#define GLD 36
__global__ __launch_bounds__(256, 2) void gemm_tf32(
    const float* __restrict__ Ain,
    const float* __restrict__ W,
    const float* __restrict__ bias,
    float* __restrict__ Cout,
    int mode)
{
    extern __shared__ float sg[];
    float* As0 = sg;
    float* As1 = sg + 128*GLD;
    float* Bs0 = sg + 2*128*GLD;
    float* Bs1 = sg + 3*128*GLD;
    float* sB  = sg + 4*128*GLD;   // 16 x 128 replicated bias

    const float* A = (mode == 0) ? Ain : g_attn;
    const int n0 = blockIdx.x * 128;
    const int m0 = blockIdx.y * 128;
    const int tid = threadIdx.x;
    const int warp = tid >> 5;
    const int wm = warp & 3;   // 0..3 -> 32 rows
    const int wn = warp >> 2;  // 0..1 -> 64 cols

    // issue one K-stage (A 128x32 + B 128x32) via cp.async
    auto issue = [&](int kt, float* as, float* bs) {
        #pragma unroll
        for (int u = 0; u < 4; u++) {
            int idx = tid + u*256;                  // 1024 float4
            int r = idx >> 3, c4 = idx & 7;
            cp16(&as[r*GLD + c4*4], &A[(size_t)(m0 + r)*768 + kt + c4*4]);
        }
        #pragma unroll
        for (int u = 0; u < 4; u++) {
            int idx = tid + u*256;
            int r = idx >> 3, c4 = idx & 7;
            cp16(&bs[r*GLD + c4*4], &W[(size_t)(n0 + r)*768 + kt + c4*4]);
        }
        CP_COMMIT();
    };

    issue(0, As0, Bs0);
    issue(32, As1, Bs1);

    // bias tile: 16 identical rows of bias[n0..n0+127]
    for (int i = tid; i < 16*128; i += 256)
        sB[i] = bias[n0 + (i & 127)];
    __syncthreads();

    wmma::fragment<wmma::accumulator,16,16,8,float> c[2][4];
    #pragma unroll
    for (int i = 0; i < 2; i++)
        #pragma unroll
        for (int j = 0; j < 4; j++)
            wmma::load_matrix_sync(c[i][j], &sB[wn*64 + j*16], 128, wmma::mem_row_major);

    for (int it = 0; it < 24; it++) {
        CP_WAIT1();
        __syncthreads();
        float* as = (it & 1) ? As1 : As0;
        float* bs = (it & 1) ? Bs1 : Bs0;

        #pragma unroll
        for (int kk = 0; kk < 32; kk += 8) {
            wmma::fragment<wmma::matrix_a,16,16,8,wmma::precision::tf32,wmma::row_major> a[2];
            wmma::fragment<wmma::matrix_b,16,16,8,wmma::precision::tf32,wmma::col_major> b[4];
            #pragma unroll
            for (int i = 0; i < 2; i++) {
                wmma::load_matrix_sync(a[i], &as[(wm*32 + i*16)*GLD + kk], GLD);
                #pragma unroll
                for (int e = 0; e < a[i].num_elements; e++)
                    a[i].x[e] = wmma::__float_to_tf32(a[i].x[e]);
            }
            #pragma unroll
            for (int j = 0; j < 4; j++) {
                wmma::load_matrix_sync(b[j], &bs[(wn*64 + j*16)*GLD + kk], GLD);
                #pragma unroll
                for (int e = 0; e < b[j].num_elements; e++)
                    b[j].x[e] = wmma::__float_to_tf32(b[j].x[e]);
            }
            #pragma unroll
            for (int i = 0; i < 2; i++)
                #pragma unroll
                for (int j = 0; j < 4; j++)
                    wmma::mma_sync(c[i][j], a[i], b[j], c[i][j]);
        }
        __syncthreads();
        if (it + 2 < 24) issue((it + 2)*32, as, bs);
        else CP_COMMIT();   // keep group accounting consistent
    }

    // direct epilogue: store fragments straight to global
    if (mode == 1) {
        #pragma unroll
        for (int i = 0; i < 2; i++)
            #pragma unroll
            for (int j = 0; j < 4; j++) {
                int m = m0 + wm*32 + i*16;
                int n = n0 + wn*64 + j*16;
                wmma::store_matrix_sync(&Cout[(size_t)m*768 + n], c[i][j], 768,
                                        wmma::mem_row_major);
            }
    } else {
        #pragma unroll
        for (int i = 0; i < 2; i++)
            #pragma unroll
            for (int j = 0; j < 4; j++) {
                // pre-round to tf32 so attention needs no cvt
                #pragma unroll
                for (int e = 0; e < c[i][j].num_elements; e++)
                    c[i][j].x[e] = __uint_as_float(f2tf(c[i][j].x[e]));
                int m = m0 + wm*32 + i*16;
                int n = n0 + wn*64 + j*16;
                int bb = m >> 10, tt = m & 1023;
                int c3 = n / 768;
                int rem = n - c3*768;
                int h = rem >> 6, d = rem & 63;
                float* dst = ((c3 == 0) ? g_q : (c3 == 1) ? g_k : g_v)
                           + ((size_t)(bb*NHEAD + h)*SEQ + tt)*64 + d;
                wmma::store_matrix_sync(dst, c[i][j], 64, wmma::mem_row_major);
            }
    }
}

// ---------------------------------------------------------------------------
// Flash attention with relative-position bias, raw mma.m16n8k8 tf32.
// grid (16 q-tiles, 48 bh), 128 threads = 4 warps, warp owns 16 q-rows.
// All accumulators / softmax state register-resident. 2 barriers per s-tile.
// K/Q smem stride 68, V stride 72 -> conflict-free fragment LDS.
// ---------------------------------------------------------------------------
#define LDK 68
#define LDV 72
#define CSC 0.18033688f   // 0.125 * log2(e)

__global__ __launch_bounds__(128, 2) void attn_flash(const float* __restrict__ rel_emb)
{
    extern __shared__ float sa[];
    float* sK0 = sa;                   // 64*68
    float* sK1 = sa + 64*LDK;
    float* sV0 = sa + 2*64*LDK;        // 64*72
    float* sV1 = sV0 + 64*LDV;
    float* sR  = sV0 + 2*64*LDV;       // 64*36 (log2-scaled rel projections)

    const int t0 = blockIdx.x * 64;
    const int bh = blockIdx.y;
    const int tid = threadIdx.x;
    const int w = tid >> 5;
    const int lane = tid & 31;
    const int g = lane >> 2;           // group id (row within 16-slab)
    const int t = lane & 3;            // thread-in-group

    const float* qb = g_q + ((size_t)bh*SEQ + t0)*64;
    const float* kb = g_k + (size_t)bh*SEQ*64;
    const float* vb = g_v + (size_t)bh*SEQ*64;

    auto issueKV = [&](int s0, float* dK, float* dV) {
        #pragma unroll
        for (int u = 0; u < 8; u++) {
            int idx = tid + u*128;           // 1024 float4 per matrix
            int r = idx >> 4, c4 = idx & 15;
            cp16(&dK[r*LDK + c4*4], &kb[(size_t)(s0 + r)*64 + c4*4]);
            cp16(&dV[r*LDV + c4*4], &vb[(size_t)(s0 + r)*64 + c4*4]);
        }
        CP_COMMIT();
    };

    issueKV(0, sK0, sV0);                              // group: stage 0
    // Q -> sK1, rel_emb -> sV1 (prologue only)
    #pragma unroll
    for (int u = 0; u < 8; u++) {
        int idx = tid + u*128;
        int r = idx >> 4, c4 = idx & 15;
        cp16(&sK1[r*LDK + c4*4], &qb[(size_t)r*64 + c4*4]);
    }
    for (int idx = tid; idx < 33*16; idx += 128) {
        int r = idx >> 4, c4 = idx & 15;
        cp16(&sV1[r*LDV + c4*4], &rel_emb[(size_t)r*64 + c4*4]);
    }
    CP_COMMIT();
    CP_WAIT0();
    __syncthreads();

    // rel projections: sR[r][j] = (Q[r] . rel[j]) * scale * log2e
    for (int idx = tid; idx < 64*33; idx += 128) {
        int r = idx / 33, j = idx - r*33;
        float acc = 0.0f;
        #pragma unroll 8
        for (int d = 0; d < 64; d++) acc += sK1[r*LDK + d] * sV1[j*LDV + d];
        sR[r*36 + j] = acc * CSC;
    }

    // persistent Q A-fragments (values already tf32-rounded by producer)
    const int r0 = w*16 + g;           // local q row (second row = r0+8)
    unsigned qa[8][4];
    #pragma unroll
    for (int kc = 0; kc < 8; kc++) {
        qa[kc][0] = __float_as_uint(sK1[r0*LDK + kc*8 + t]);
        qa[kc][1] = __float_as_uint(sK1[(r0+8)*LDK + kc*8 + t]);
        qa[kc][2] = __float_as_uint(sK1[r0*LDK + kc*8 + t + 4]);
        qa[kc][3] = __float_as_uint(sK1[(r0+8)*LDK + kc*8 + t + 4]);
    }
    __syncthreads();                   // sR ready; sK1/sV1 free
    issueKV(64, sK1, sV1);             // stage 1

    float o[8][4];
    #pragma unroll
    for (int i = 0; i < 8; i++)
        #pragma unroll
        for (int j = 0; j < 4; j++) o[i][j] = 0.0f;
    float m0v = -INFINITY, m1v = -INFINITY, l0 = 0.0f, l1 = 0.0f;

    const int rowt0 = t0 + r0, rowt1 = rowt0 + 8;

    for (int it = 0; it < 16; it++) {
        if (it == 15) CP_WAIT0(); else CP_WAIT1();
        __syncthreads();
        const float* cK = (it & 1) ? sK1 : sK0;
        const float* cV = (it & 1) ? sV1 : sV0;
        const int s0 = it * 64;

        // S = Q @ K^T   (16 x 64 per warp)
        float s[8][4];
        #pragma unroll
        for (int nf = 0; nf < 8; nf++) {
            s[nf][0] = s[nf][1] = s[nf][2] = s[nf][3] = 0.0f;
            const float* kp = cK + (nf*8 + g)*LDK;
            #pragma unroll
            for (int kc = 0; kc < 8; kc++) {
                unsigned b0 = __float_as_uint(kp[kc*8 + t]);
                unsigned b1 = __float_as_uint(kp[kc*8 + t + 4]);
                mma8(s[nf], qa[kc], b0, b1);
            }
        }

        // bias + scale (log2 domain), row maxes
        const bool uni = (s0 >= t0 + 128) || (s0 + 128 <= t0);
        float bc0 = 0.0f, bc1 = 0.0f;
        if (uni) {
            int jj = (s0 > t0) ? 32 : 0;
            bc0 = sR[r0*36 + jj];
            bc1 = sR[(r0+8)*36 + jj];
        }
        float mn0 = -INFINITY, mn1 = -INFINITY;
        #pragma unroll
        for (int nf = 0; nf < 8; nf++) {
            int cc = s0 + nf*8 + 2*t;
            if (uni) {
                s[nf][0] = s[nf][0]*CSC + bc0;
                s[nf][1] = s[nf][1]*CSC + bc0;
                s[nf][2] = s[nf][2]*CSC + bc1;
                s[nf][3] = s[nf][3]*CSC + bc1;
            } else {
                int d00 = cc - rowt0;     d00 = d00 < -16 ? -16 : (d00 > 16 ? 16 : d00);
                int d01 = cc + 1 - rowt0; d01 = d01 < -16 ? -16 : (d01 > 16 ? 16 : d01);
                int d10 = cc - rowt1;     d10 = d10 < -16 ? -16 : (d10 > 16 ? 16 : d10);
                int d11 = cc + 1 - rowt1; d11 = d11 < -16 ? -16 : (d11 > 16 ? 16 : d11);
                s[nf][0] = s[nf][0]*CSC + sR[r0*36 + d00 + 16];
                s[nf][1] = s[nf][1]*CSC + sR[r0*36 + d01 + 16];
                s[nf][2] = s[nf][2]*CSC + sR[(r0+8)*36 + d10 + 16];
                s[nf][3] = s[nf][3]*CSC + sR[(r0+8)*36 + d11 + 16];
            }
            mn0 = fmaxf(mn0, fmaxf(s[nf][0], s[nf][1]));
            mn1 = fmaxf(mn1, fmaxf(s[nf][2], s[nf][3]));
        }
        mn0 = fmaxf(mn0, __shfl_xor_sync(0xffffffffu, mn0, 1));
        mn0 = fmaxf(mn0, __shfl_xor_sync(0xffffffffu, mn0, 2));
        mn1 = fmaxf(mn1, __shfl_xor_sync(0xffffffffu, mn1, 1));
        mn1 = fmaxf(mn1, __shfl_xor_sync(0xffffffffu, mn1, 2));
        float m0n = fmaxf(m0v, mn0);
        float m1n = fmaxf(m1v, mn1);
        float a0 = ex2(m0v - m0n);
        float a1 = ex2(m1v - m1n);
        m0v = m0n; m1v = m1n;

        // P = exp2(val - m), sum l, convert to tf32, rescale O
        float ls0 = 0.0f, ls1 = 0.0f;
        unsigned pu[8][4];
        #pragma unroll
        for (int nf = 0; nf < 8; nf++) {
            float p00 = ex2(s[nf][0] - m0n);
            float p01 = ex2(s[nf][1] - m0n);
            float p10 = ex2(s[nf][2] - m1n);
            float p11 = ex2(s[nf][3] - m1n);
            ls0 += p00 + p01;
            ls1 += p10 + p11;
            pu[nf][0] = f2tf(p00);
            pu[nf][1] = f2tf(p01);
            pu[nf][2] = f2tf(p10);
            pu[nf][3] = f2tf(p11);
        }
        ls0 += __shfl_xor_sync(0xffffffffu, ls0, 1);
        ls0 += __shfl_xor_sync(0xffffffffu, ls0, 2);
        ls1 += __shfl_xor_sync(0xffffffffu, ls1, 1);
        ls1 += __shfl_xor_sync(0xffffffffu, ls1, 2);
        l0 = l0*a0 + ls0;
        l1 = l1*a1 + ls1;
        #pragma unroll
        for (int dn = 0; dn < 8; dn++) {
            o[dn][0] *= a0; o[dn][1] *= a0;
            o[dn][2] *= a1; o[dn][3] *= a1;
        }

        // permute P accumulator layout (cols 2t,2t+1) -> A-fragment layout (t, t+4)
        unsigned pa[8][4];
        const int lo = (lane & ~3) | (t >> 1);
        const int hi = lo + 2;
        #pragma unroll
        for (int nf = 0; nf < 8; nf++) {
            unsigned x0 = __shfl_sync(0xffffffffu, pu[nf][0], lo);
            unsigned x1 = __shfl_sync(0xffffffffu, pu[nf][1], lo);
            unsigned y0 = __shfl_sync(0xffffffffu, pu[nf][0], hi);
            unsigned y1 = __shfl_sync(0xffffffffu, pu[nf][1], hi);
            pa[nf][0] = (t & 1) ? x1 : x0;
            pa[nf][2] = (t & 1) ? y1 : y0;
            unsigned z0 = __shfl_sync(0xffffffffu, pu[nf][2], lo);
            unsigned z1 = __shfl_sync(0xffffffffu, pu[nf][3], lo);
            unsigned u0 = __shfl_sync(0xffffffffu, pu[nf][2], hi);
            unsigned u1 = __shfl_sync(0xffffffffu, pu[nf][3], hi);
            pa[nf][1] = (t & 1) ? z1 : z0;
            pa[nf][3] = (t & 1) ? u1 : u0;
        }

        // O += P @ V   (16 x 64)
        #pragma unroll
        for (int dn = 0; dn < 8; dn++) {
            #pragma unroll
            for (int kc = 0; kc < 8; kc++) {
                unsigned b0 = __float_as_uint(cV[(kc*8 + t)*LDV + dn*8 + g]);
                unsigned b1 = __float_as_uint(cV[(kc*8 + t + 4)*LDV + dn*8 + g]);
                mma8(o[dn], pa[kc], b0, b1);
            }
        }
        __syncthreads();
        if (it + 2 < 16) issueKV((it + 2)*64, (it & 1) ? sK1 : sK0, (it & 1) ? sV1 : sV0);
        else CP_COMMIT();
    }

    // epilogue: normalize, write [B,T,H*64]
    const int bb = bh / NHEAD, h = bh - bb*NHEAD;
    const float inv0 = 1.0f / l0;
    const float inv1 = 1.0f / l1;
    float* o0 = g_attn + ((size_t)(bb*SEQ + t0 + r0))*D_MODEL + h*64;
    float* o1 = o0 + (size_t)8*D_MODEL;
    #pragma unroll
    for (int dn = 0; dn < 8; dn++) {
        *(float2*)(o0 + dn*8 + 2*t) = make_float2(o[dn][0]*inv0, o[dn][1]*inv0);
        *(float2*)(o1 + dn*8 + 2*t) = make_float2(o[dn][2]*inv1, o[dn][3]*inv1);
    }
}

// ---------------------------------------------------------------------------
extern "C" void kernel_launch(void* const* d_in, const int* in_sizes, int n_in,
                              void* d_out, int out_size)
{
    const float* x     = (const float*)d_in[0];
    const float* qkv_w = (const float*)d_in[1];
    const float* qkv_b = (const float*)d_in[2];
    const float* out_w = (const float*)d_in[3];
    const float* out_b = (const float*)d_in[4];
    const float* rel   = (const float*)d_in[5];
    float* out = (float*)d_out;

    (void)in_sizes; (void)n_in; (void)out_size;

    const int gemm_smem = (4*128*GLD + 16*128) * 4;                 // 81920 B
    const int attn_smem = (2*64*LDK + 2*64*LDV + 64*36) * 4;        // 80896 B
    cudaFuncSetAttribute(gemm_tf32, cudaFuncAttributeMaxDynamicSharedMemorySize, gemm_smem);
    cudaFuncSetAttribute(attn_flash, cudaFuncAttributeMaxDynamicSharedMemorySize, attn_smem);

    // 1) QKV projection -> q/k/v [B,H,T,64], tf32-pre-rounded
    gemm_tf32<<<dim3(18, 32), 256, gemm_smem>>>(x, qkv_w, qkv_b, nullptr, 0);
    // 2) fused flash attention with relative-position bias
    attn_flash<<<dim3(16, 48), 128, attn_smem>>>(rel);
    // 3) output projection
    gemm_tf32<<<dim3(6, 32), 256, gemm_smem>>>(nullptr, out_w, out_b, out, 1);
}

// round 7
// speedup vs baseline: 3.0292x; 1.8056x over previous
#include <cuda_runtime.h>
#include <cuda_fp16.h>
#include <math.h>

#define D_MODEL 768
#define NHEAD 12
#define HEAD_DIM 64
#define BATCH 4
#define SEQ 1024
#define MTOT (BATCH*SEQ)

// scratch (allocation-free requirement -> device globals)
__device__ __half g_xh[MTOT*D_MODEL];
__device__ __half g_wqkvh[3*D_MODEL*D_MODEL];
__device__ __half g_wouth[D_MODEL*D_MODEL];
__device__ __half g_qh[BATCH*NHEAD*SEQ*HEAD_DIM];
__device__ __half g_kh[BATCH*NHEAD*SEQ*HEAD_DIM];
__device__ __half g_vh[BATCH*NHEAD*SEQ*HEAD_DIM];
__device__ __half g_attnh[MTOT*D_MODEL];

// ---------------------------------------------------------------------------
// helpers
// ---------------------------------------------------------------------------
__device__ __forceinline__ void cp16(void* s, const void* g) {
    unsigned sa = (unsigned)__cvta_generic_to_shared(s);
    asm volatile("cp.async.cg.shared.global [%0], [%1], 16;" :: "r"(sa), "l"(g));
}
#define CP_COMMIT() asm volatile("cp.async.commit_group;")
#define CP_WAIT1()  asm volatile("cp.async.wait_group 1;")
#define CP_WAIT0()  asm volatile("cp.async.wait_group 0;")

__device__ __forceinline__ float ex2(float x) {
    float r;
    asm("ex2.approx.ftz.f32 %0, %1;" : "=f"(r) : "f"(x));
    return r;
}

// bit-cast __half2 -> u32 (register reinterpret, no instruction)
__device__ __forceinline__ unsigned h2u(__half2 h) {
    __half2_raw hr = *(__half2_raw*)&h;
    unsigned u = (unsigned)hr.x | ((unsigned)hr.y << 16);
    return u;
}

// mma.m16n8k16 f16 inputs, f32 accum. Documented fragment layouts:
// A: a0=(row g, k=2t,2t+1) a1=(g+8, same) a2=(g, k+8) a3=(g+8, k+8)   [half2]
// B: b0=(k=2t,2t+1, col g) b1=(k=2t+8,+9, col g)
// C: c0=(g,2t) c1=(g,2t+1) c2=(g+8,2t) c3=(g+8,2t+1)
__device__ __forceinline__ void mma16(float* d, const unsigned* a, unsigned b0, unsigned b1) {
    asm volatile(
        "mma.sync.aligned.m16n8k16.row.col.f32.f16.f16.f32 "
        "{%0,%1,%2,%3}, {%4,%5,%6,%7}, {%8,%9}, {%0,%1,%2,%3};"
        : "+f"(d[0]), "+f"(d[1]), "+f"(d[2]), "+f"(d[3])
        : "r"(a[0]), "r"(a[1]), "r"(a[2]), "r"(a[3]), "r"(b0), "r"(b1));
}

__device__ __forceinline__ unsigned pack2(__half lo, __half hi) {
    return (unsigned)__half_as_ushort(lo) | ((unsigned)__half_as_ushort(hi) << 16);
}

// ---------------------------------------------------------------------------
// fp32 -> fp16 conversion pre-pass (which: 0=x, 1=qkv_w, 2=out_w)
// ---------------------------------------------------------------------------
__global__ void to_half(const float* __restrict__ src, int which, int n4)
{
    __half* dst = (which == 0) ? g_xh : (which == 1) ? g_wqkvh : g_wouth;
    int i = blockIdx.x * blockDim.x + threadIdx.x;
    if (i < n4) {
        float4 v = ((const float4*)src)[i];
        __half2* d2 = (__half2*)dst;
        d2[i*2]   = __floats2half2_rn(v.x, v.y);
        d2[i*2+1] = __floats2half2_rn(v.z, v.w);
    }
}

// ---------------------------------------------------------------------------
// fp16 GEMM: C[m,n] = sum_k A[m,k]*W[n,k] + bias[n]
// Block 128x128, K-chunk 64 halves, cp.async double-buffered, 256 thr (8 warps),
// warp tile 32x64 via raw mma.m16n8k16 (2 m-frags x 8 n-frags x 4 k-steps).
// mode 0: A = g_xh,    epilogue -> half, scattered into g_qh/g_kh/g_vh [B,H,T,64]
// mode 1: A = g_attnh, epilogue -> f32 Cout row-major [4096,768]
// ---------------------------------------------------------------------------
#define LDH 72
__global__ __launch_bounds__(256, 2) void gemm_half(
    const float* __restrict__ bias,
    float* __restrict__ Cout,
    int mode)
{
    extern __shared__ __align__(16) char smraw[];
    __half* hA0 = (__half*)smraw;                 // 128 x 72 halves
    __half* hA1 = hA0 + 128*LDH;
    __half* hB0 = hA1 + 128*LDH;
    __half* hB1 = hB0 + 128*LDH;
    float*  sBias = (float*)(hB1 + 128*LDH);      // 128 floats

    const __half* A = (mode == 0) ? g_xh : g_attnh;
    const __half* W = (mode == 0) ? g_wqkvh : g_wouth;

    const int n0 = blockIdx.x * 128;
    const int m0 = blockIdx.y * 128;
    const int tid = threadIdx.x;
    const int warp = tid >> 5;
    const int lane = tid & 31;
    const int g = lane >> 2;
    const int t = lane & 3;
    const int wm = warp & 3;   // 4 m-slabs of 32
    const int wn = warp >> 2;  // 2 n-slabs of 64

    auto issue = [&](int kt, __half* as, __half* bs) {
        #pragma unroll
        for (int u = 0; u < 4; u++) {
            int idx = tid + u*256;               // 1024 x 16B for A
            int r = idx >> 3, c8 = idx & 7;
            cp16(&as[r*LDH + c8*8], &A[(size_t)(m0 + r)*768 + kt + c8*8]);
        }
        #pragma unroll
        for (int u = 0; u < 4; u++) {
            int idx = tid + u*256;
            int r = idx >> 3, c8 = idx & 7;
            cp16(&bs[r*LDH + c8*8], &W[(size_t)(n0 + r)*768 + kt + c8*8]);
        }
        CP_COMMIT();
    };

    issue(0, hA0, hB0);
    issue(64, hA1, hB1);
    if (tid < 128) sBias[tid] = bias[n0 + tid];

    float c[2][8][4];
    #pragma unroll
    for (int mf = 0; mf < 2; mf++)
        #pragma unroll
        for (int nf = 0; nf < 8; nf++)
            #pragma unroll
            for (int e = 0; e < 4; e++) c[mf][nf][e] = 0.0f;

    for (int it = 0; it < 12; it++) {
        CP_WAIT1();
        __syncthreads();
        const __half* as = (it & 1) ? hA1 : hA0;
        const __half* bs = (it & 1) ? hB1 : hB0;

        #pragma unroll
        for (int kc = 0; kc < 4; kc++) {
            unsigned a[2][4];
            #pragma unroll
            for (int mf = 0; mf < 2; mf++) {
                const __half* ap = as + (wm*32 + mf*16 + g)*LDH + kc*16 + 2*t;
                a[mf][0] = *(const unsigned*)ap;
                a[mf][1] = *(const unsigned*)(ap + 8*LDH);
                a[mf][2] = *(const unsigned*)(ap + 8);
                a[mf][3] = *(const unsigned*)(ap + 8*LDH + 8);
            }
            #pragma unroll
            for (int nf = 0; nf < 8; nf++) {
                const __half* bp = bs + (wn*64 + nf*8 + g)*LDH + kc*16 + 2*t;
                unsigned b0 = *(const unsigned*)bp;
                unsigned b1 = *(const unsigned*)(bp + 8);
                mma16(c[0][nf], a[0], b0, b1);
                mma16(c[1][nf], a[1], b0, b1);
            }
        }
        __syncthreads();
        if (it + 2 < 12) issue((it + 2)*64, (it & 1) ? hA1 : hA0, (it & 1) ? hB1 : hB0);
        else CP_COMMIT();
    }

    // epilogue: direct stores, known fragment layout
    #pragma unroll
    for (int mf = 0; mf < 2; mf++) {
        #pragma unroll
        for (int nf = 0; nf < 8; nf++) {
            int m = m0 + wm*32 + mf*16 + g;       // rows m and m+8 (same 1024-block)
            int n = n0 + wn*64 + nf*8 + 2*t;
            float bv0 = sBias[n - n0], bv1 = sBias[n - n0 + 1];
            float v00 = c[mf][nf][0] + bv0, v01 = c[mf][nf][1] + bv1;   // row m
            float v10 = c[mf][nf][2] + bv0, v11 = c[mf][nf][3] + bv1;   // row m+8
            if (mode == 1) {
                *(float2*)&Cout[(size_t)m*768 + n]     = make_float2(v00, v01);
                *(float2*)&Cout[(size_t)(m+8)*768 + n] = make_float2(v10, v11);
            } else {
                int c3 = n / 768;
                int rem = n - c3*768;
                int h = rem >> 6, d = rem & 63;
                __half* dst = (c3 == 0) ? g_qh : (c3 == 1) ? g_kh : g_vh;
                int bb = m >> 10, tt = m & 1023;
                size_t rowbase = ((size_t)(bb*NHEAD + h)*SEQ + tt)*64 + d;
                *(__half2*)&dst[rowbase]        = __floats2half2_rn(v00, v01);
                *(__half2*)&dst[rowbase + 8*64] = __floats2half2_rn(v10, v11);
            }
        }
    }
}

// ---------------------------------------------------------------------------
// Flash attention with relative-position bias, fp16 mma.m16n8k16.
// grid (16 q-tiles, 48 bh), 128 threads = 4 warps, warp owns 16 q-rows.
// No shuffles: P accumulator packs directly into A operand (f16 layout match).
// ---------------------------------------------------------------------------
#define LDKH 72
#define CSC 0.18033688f   // 0.125 * log2(e)

__global__ __launch_bounds__(128, 3) void attn_flash(const float* __restrict__ rel_emb)
{
    extern __shared__ __align__(16) char saraw[];
    __half* sK0 = (__half*)saraw;               // 64 x 72 halves
    __half* sK1 = sK0 + 64*LDKH;
    __half* sV0 = sK1 + 64*LDKH;
    __half* sV1 = sV0 + 64*LDKH;
    float*  sR  = (float*)(sV1 + 64*LDKH);      // 64 x 36 floats

    const int t0 = blockIdx.x * 64;
    const int bh = blockIdx.y;
    const int tid = threadIdx.x;
    const int w = tid >> 5;
    const int lane = tid & 31;
    const int g = lane >> 2;
    const int t = lane & 3;

    const __half* qb = g_qh + ((size_t)bh*SEQ + t0)*64;
    const __half* kb = g_kh + (size_t)bh*SEQ*64;
    const __half* vb = g_vh + (size_t)bh*SEQ*64;

    auto issueKV = [&](int s0, __half* dK, __half* dV) {
        #pragma unroll
        for (int u = 0; u < 4; u++) {
            int idx = tid + u*128;               // 512 x 16B per matrix
            int r = idx >> 3, c8 = idx & 7;
            cp16(&dK[r*LDKH + c8*8], &kb[(size_t)(s0 + r)*64 + c8*8]);
            cp16(&dV[r*LDKH + c8*8], &vb[(size_t)(s0 + r)*64 + c8*8]);
        }
        CP_COMMIT();
    };

    issueKV(0, sK0, sV0);                          // group: stage 0
    // Q (half) -> sK1 ; rel_emb (fp32, 8448 B) -> sV1 region
    float* relbuf = (float*)sV1;
    #pragma unroll
    for (int u = 0; u < 4; u++) {
        int idx = tid + u*128;
        int r = idx >> 3, c8 = idx & 7;
        cp16(&sK1[r*LDKH + c8*8], &qb[(size_t)r*64 + c8*8]);
    }
    for (int idx = tid; idx < 33*16; idx += 128)
        cp16(&relbuf[idx*4], &rel_emb[(size_t)idx*4]);
    CP_COMMIT();
    CP_WAIT0();
    __syncthreads();

    // rel projections: sR[r][j] = (Q[r] . rel[j]) * scale * log2e
    for (int idx = tid; idx < 64*33; idx += 128) {
        int r = idx / 33, j = idx - r*33;
        const __half2* qr = (const __half2*)&sK1[r*LDKH];
        const float* rp = &relbuf[j*64];
        float acc = 0.0f;
        #pragma unroll 8
        for (int d = 0; d < 32; d++) {
            float2 qf = __half22float2(qr[d]);
            acc += qf.x*rp[2*d] + qf.y*rp[2*d+1];
        }
        sR[r*36 + j] = acc * CSC;
    }

    // persistent Q A-fragments
    const int r0 = w*16 + g;
    unsigned qa[4][4];
    #pragma unroll
    for (int kc = 0; kc < 4; kc++) {
        const __half* qp = sK1 + r0*LDKH + kc*16 + 2*t;
        qa[kc][0] = *(const unsigned*)qp;
        qa[kc][1] = *(const unsigned*)(qp + 8*LDKH);
        qa[kc][2] = *(const unsigned*)(qp + 8);
        qa[kc][3] = *(const unsigned*)(qp + 8*LDKH + 8);
    }
    __syncthreads();                 // sR ready; sK1/sV1 free
    issueKV(64, sK1, sV1);           // stage 1

    float o[8][4];
    #pragma unroll
    for (int i = 0; i < 8; i++)
        #pragma unroll
        for (int j = 0; j < 4; j++) o[i][j] = 0.0f;
    float m0v = -INFINITY, m1v = -INFINITY, l0 = 0.0f, l1 = 0.0f;

    const int rowt0 = t0 + r0, rowt1 = rowt0 + 8;

    for (int it = 0; it < 16; it++) {
        if (it == 15) CP_WAIT0(); else CP_WAIT1();
        __syncthreads();
        const __half* cK = (it & 1) ? sK1 : sK0;
        const __half* cV = (it & 1) ? sV1 : sV0;
        const int s0 = it * 64;

        // S = Q @ K^T   (16 x 64 per warp)
        float s[8][4];
        #pragma unroll
        for (int nf = 0; nf < 8; nf++) {
            s[nf][0] = s[nf][1] = s[nf][2] = s[nf][3] = 0.0f;
            const __half* kp = cK + (nf*8 + g)*LDKH;
            #pragma unroll
            for (int kc = 0; kc < 4; kc++) {
                unsigned b0 = *(const unsigned*)(kp + kc*16 + 2*t);
                unsigned b1 = *(const unsigned*)(kp + kc*16 + 2*t + 8);
                mma16(s[nf], qa[kc], b0, b1);
            }
        }

        // bias + scale (log2 domain), row maxes
        const bool uni = (s0 >= t0 + 128) || (s0 + 128 <= t0);
        float bc0 = 0.0f, bc1 = 0.0f;
        if (uni) {
            int jj = (s0 > t0) ? 32 : 0;
            bc0 = sR[r0*36 + jj];
            bc1 = sR[(r0+8)*36 + jj];
        }
        float mn0 = -INFINITY, mn1 = -INFINITY;
        #pragma unroll
        for (int nf = 0; nf < 8; nf++) {
            int cc = s0 + nf*8 + 2*t;
            if (uni) {
                s[nf][0] = s[nf][0]*CSC + bc0;
                s[nf][1] = s[nf][1]*CSC + bc0;
                s[nf][2] = s[nf][2]*CSC + bc1;
                s[nf][3] = s[nf][3]*CSC + bc1;
            } else {
                int d00 = cc - rowt0;     d00 = d00 < -16 ? -16 : (d00 > 16 ? 16 : d00);
                int d01 = cc + 1 - rowt0; d01 = d01 < -16 ? -16 : (d01 > 16 ? 16 : d01);
                int d10 = cc - rowt1;     d10 = d10 < -16 ? -16 : (d10 > 16 ? 16 : d10);
                int d11 = cc + 1 - rowt1; d11 = d11 < -16 ? -16 : (d11 > 16 ? 16 : d11);
                s[nf][0] = s[nf][0]*CSC + sR[r0*36 + d00 + 16];
                s[nf][1] = s[nf][1]*CSC + sR[r0*36 + d01 + 16];
                s[nf][2] = s[nf][2]*CSC + sR[(r0+8)*36 + d10 + 16];
                s[nf][3] = s[nf][3]*CSC + sR[(r0+8)*36 + d11 + 16];
            }
            mn0 = fmaxf(mn0, fmaxf(s[nf][0], s[nf][1]));
            mn1 = fmaxf(mn1, fmaxf(s[nf][2], s[nf][3]));
        }
        mn0 = fmaxf(mn0, __shfl_xor_sync(0xffffffffu, mn0, 1));
        mn0 = fmaxf(mn0, __shfl_xor_sync(0xffffffffu, mn0, 2));
        mn1 = fmaxf(mn1, __shfl_xor_sync(0xffffffffu, mn1, 1));
        mn1 = fmaxf(mn1, __shfl_xor_sync(0xffffffffu, mn1, 2));
        float m0n = fmaxf(m0v, mn0);
        float m1n = fmaxf(m1v, mn1);
        float a0 = ex2(m0v - m0n);
        float a1 = ex2(m1v - m1n);
        m0v = m0n; m1v = m1n;

        // P = exp2(val - m); pack straight into f16 A-operand layout (no shuffles)
        float ls0 = 0.0f, ls1 = 0.0f;
        unsigned ph[8][2];
        #pragma unroll
        for (int nf = 0; nf < 8; nf++) {
            float p00 = ex2(s[nf][0] - m0n);
            float p01 = ex2(s[nf][1] - m0n);
            float p10 = ex2(s[nf][2] - m1n);
            float p11 = ex2(s[nf][3] - m1n);
            ls0 += p00 + p01;
            ls1 += p10 + p11;
            ph[nf][0] = h2u(__floats2half2_rn(p00, p01));  // row g
            ph[nf][1] = h2u(__floats2half2_rn(p10, p11));  // row g+8
        }
        ls0 += __shfl_xor_sync(0xffffffffu, ls0, 1);
        ls0 += __shfl_xor_sync(0xffffffffu, ls0, 2);
        ls1 += __shfl_xor_sync(0xffffffffu, ls1, 1);
        ls1 += __shfl_xor_sync(0xffffffffu, ls1, 2);
        l0 = l0*a0 + ls0;
        l1 = l1*a1 + ls1;
        #pragma unroll
        for (int dn = 0; dn < 8; dn++) {
            o[dn][0] *= a0; o[dn][1] *= a0;
            o[dn][2] *= a1; o[dn][3] *= a1;
        }

        // O += P @ V   (16 x 64); A from ph, B packed from two V rows
        #pragma unroll
        for (int kc = 0; kc < 4; kc++) {
            unsigned a[4] = { ph[2*kc][0], ph[2*kc][1], ph[2*kc+1][0], ph[2*kc+1][1] };
            const __half* v0 = cV + (kc*16 + 2*t)*LDKH;      // k = 2t
            const __half* v1 = v0 + LDKH;                    // k = 2t+1
            const __half* v2 = v0 + 8*LDKH;                  // k = 2t+8
            const __half* v3 = v2 + LDKH;                    // k = 2t+9
            #pragma unroll
            for (int dn = 0; dn < 8; dn++) {
                int dc = dn*8 + g;
                unsigned b0 = pack2(v0[dc], v1[dc]);
                unsigned b1 = pack2(v2[dc], v3[dc]);
                mma16(o[dn], a, b0, b1);
            }
        }
        __syncthreads();
        if (it + 2 < 16) issueKV((it + 2)*64, (it & 1) ? sK1 : sK0, (it & 1) ? sV1 : sV0);
        else CP_COMMIT();
    }

    // epilogue: normalize, write half [B,T,H*64]
    const int bb = bh / NHEAD, h = bh - bb*NHEAD;
    const float inv0 = 1.0f / l0;
    const float inv1 = 1.0f / l1;
    __half* o0 = g_attnh + ((size_t)(bb*SEQ + t0 + r0))*D_MODEL + h*64;
    __half* o1 = o0 + (size_t)8*D_MODEL;
    #pragma unroll
    for (int dn = 0; dn < 8; dn++) {
        *(__half2*)(o0 + dn*8 + 2*t) = __floats2half2_rn(o[dn][0]*inv0, o[dn][1]*inv0);
        *(__half2*)(o1 + dn*8 + 2*t) = __floats2half2_rn(o[dn][2]*inv1, o[dn][3]*inv1);
    }
}

// ---------------------------------------------------------------------------
extern "C" void kernel_launch(void* const* d_in, const int* in_sizes, int n_in,
                              void* d_out, int out_size)
{
    const float* x     = (const float*)d_in[0];
    const float* qkv_w = (const float*)d_in[1];
    const float* qkv_b = (const float*)d_in[2];
    const float* out_w = (const float*)d_in[3];
    const float* out_b = (const float*)d_in[4];
    const float* rel   = (const float*)d_in[5];
    float* out = (float*)d_out;

    (void)in_sizes; (void)n_in; (void)out_size;

    const int gemm_smem = (4*128*LDH)*2 + 128*4;                  // 74,240 B
    const int attn_smem = (4*64*LDKH)*2 + 64*36*4;                // 46,080 B
    cudaFuncSetAttribute(gemm_half, cudaFuncAttributeMaxDynamicSharedMemorySize, gemm_smem);
    cudaFuncSetAttribute(attn_flash, cudaFuncAttributeMaxDynamicSharedMemorySize, attn_smem);

    // 0) fp32 -> fp16 conversion pre-pass
    to_half<<<(MTOT*D_MODEL/4 + 255)/256, 256>>>(x, 0, MTOT*D_MODEL/4);
    to_half<<<(3*D_MODEL*D_MODEL/4 + 255)/256, 256>>>(qkv_w, 1, 3*D_MODEL*D_MODEL/4);
    to_half<<<(D_MODEL*D_MODEL/4 + 255)/256, 256>>>(out_w, 2, D_MODEL*D_MODEL/4);
    // 1) QKV projection -> half q/k/v [B,H,T,64]
    gemm_half<<<dim3(18, 32), 256, gemm_smem>>>(qkv_b, nullptr, 0);
    // 2) fused flash attention with relative-position bias
    attn_flash<<<dim3(16, 48), 128, attn_smem>>>(rel);
    // 3) output projection
    gemm_half<<<dim3(6, 32), 256, gemm_smem>>>(out_b, out, 1);
}

// round 9
// speedup vs baseline: 3.2237x; 1.0642x over previous
#include <cuda_runtime.h>
#include <cuda_fp16.h>
#include <math.h>

#define D_MODEL 768
#define NHEAD 12
#define HEAD_DIM 64
#define BATCH 4
#define SEQ 1024
#define MTOT (BATCH*SEQ)

// scratch (allocation-free requirement -> device globals)
__device__ __half g_xh[MTOT*D_MODEL];
__device__ __half g_wqkvh[3*D_MODEL*D_MODEL];
__device__ __half g_wouth[D_MODEL*D_MODEL];
__device__ __half g_qh[BATCH*NHEAD*SEQ*HEAD_DIM];
__device__ __half g_kh[BATCH*NHEAD*SEQ*HEAD_DIM];
__device__ __half g_vh[BATCH*NHEAD*SEQ*HEAD_DIM];
__device__ __half g_attnh[MTOT*D_MODEL];

// ---------------------------------------------------------------------------
// helpers
// ---------------------------------------------------------------------------
__device__ __forceinline__ void cp16(void* s, const void* g) {
    unsigned sa = (unsigned)__cvta_generic_to_shared(s);
    asm volatile("cp.async.cg.shared.global [%0], [%1], 16;" :: "r"(sa), "l"(g));
}
#define CP_COMMIT() asm volatile("cp.async.commit_group;")
#define CP_WAIT1()  asm volatile("cp.async.wait_group 1;")
#define CP_WAIT0()  asm volatile("cp.async.wait_group 0;")

__device__ __forceinline__ float ex2(float x) {
    float r;
    asm("ex2.approx.ftz.f32 %0, %1;" : "=f"(r) : "f"(x));
    return r;
}

// bit-cast __half2 -> u32 (register reinterpret, no instruction)
__device__ __forceinline__ unsigned h2u(__half2 h) {
    __half2_raw hr = *(__half2_raw*)&h;
    unsigned u = (unsigned)hr.x | ((unsigned)hr.y << 16);
    return u;
}

// warp-collective 8x8 b16 matrix loads (4 matrices per call)
__device__ __forceinline__ void ldsm4(unsigned& r0, unsigned& r1, unsigned& r2,
                                      unsigned& r3, unsigned addr) {
    asm volatile("ldmatrix.sync.aligned.m8n8.x4.shared.b16 {%0,%1,%2,%3}, [%4];"
                 : "=r"(r0), "=r"(r1), "=r"(r2), "=r"(r3) : "r"(addr));
}
__device__ __forceinline__ void ldsm4t(unsigned& r0, unsigned& r1, unsigned& r2,
                                       unsigned& r3, unsigned addr) {
    asm volatile("ldmatrix.sync.aligned.m8n8.x4.trans.shared.b16 {%0,%1,%2,%3}, [%4];"
                 : "=r"(r0), "=r"(r1), "=r"(r2), "=r"(r3) : "r"(addr));
}

// mma.m16n8k16 f16 inputs, f32 accum. Documented fragment layouts:
// A: a0=(row g, k=2t,2t+1) a1=(g+8, same) a2=(g, k+8) a3=(g+8, k+8)   [half2]
// B: b0=(k=2t,2t+1, col g) b1=(k=2t+8,+9, col g)
// C: c0=(g,2t) c1=(g,2t+1) c2=(g+8,2t) c3=(g+8,2t+1)
__device__ __forceinline__ void mma16(float* d, const unsigned* a, unsigned b0, unsigned b1) {
    asm volatile(
        "mma.sync.aligned.m16n8k16.row.col.f32.f16.f16.f32 "
        "{%0,%1,%2,%3}, {%4,%5,%6,%7}, {%8,%9}, {%0,%1,%2,%3};"
        : "+f"(d[0]), "+f"(d[1]), "+f"(d[2]), "+f"(d[3])
        : "r"(a[0]), "r"(a[1]), "r"(a[2]), "r"(a[3]), "r"(b0), "r"(b1));
}

// ---------------------------------------------------------------------------
// fp32 -> fp16 conversion pre-pass (which: 0=x, 1=qkv_w, 2=out_w)
// ---------------------------------------------------------------------------
__global__ void to_half(const float* __restrict__ src, int which, int n4)
{
    __half* dst = (which == 0) ? g_xh : (which == 1) ? g_wqkvh : g_wouth;
    int i = blockIdx.x * blockDim.x + threadIdx.x;
    if (i < n4) {
        float4 v = ((const float4*)src)[i];
        __half2* d2 = (__half2*)dst;
        d2[i*2]   = __floats2half2_rn(v.x, v.y);
        d2[i*2+1] = __floats2half2_rn(v.z, v.w);
    }
}

// ---------------------------------------------------------------------------
// fp16 GEMM: C[m,n] = sum_k A[m,k]*W[n,k] + bias[n]
// Block 128x128, K-chunk 64, cp.async double-buffered, 256 thr (8 warps),
// warp tile 32x64, all operand fetches via ldmatrix.x4.
// mode 0: A = g_xh,    epilogue -> half, scattered into g_qh/g_kh/g_vh [B,H,T,64]
// mode 1: A = g_attnh, epilogue -> f32 Cout row-major [4096,768]
// ---------------------------------------------------------------------------
#define LDH 72
__global__ __launch_bounds__(256, 2) void gemm_half(
    const float* __restrict__ bias,
    float* __restrict__ Cout,
    int mode)
{
    extern __shared__ __align__(16) char smraw[];
    __half* hA0 = (__half*)smraw;                 // 128 x 72 halves
    __half* hA1 = hA0 + 128*LDH;
    __half* hB0 = hA1 + 128*LDH;
    __half* hB1 = hB0 + 128*LDH;
    float*  sBias = (float*)(hB1 + 128*LDH);      // 128 floats

    const __half* A = (mode == 0) ? g_xh : g_attnh;
    const __half* W = (mode == 0) ? g_wqkvh : g_wouth;

    const int n0 = blockIdx.x * 128;
    const int m0 = blockIdx.y * 128;
    const int tid = threadIdx.x;
    const int warp = tid >> 5;
    const int lane = tid & 31;
    const int g = lane >> 2;
    const int t = lane & 3;
    const int wm = warp & 3;   // 4 m-slabs of 32
    const int wn = warp >> 2;  // 2 n-slabs of 64

    // ldmatrix lane address components (bytes)
    const int lmat = lane >> 3, lrow = lane & 7;
    // A x4: m0=(rows+0,klo) m1=(rows+8,klo) m2=(rows+0,khi) m3=(rows+8,khi)
    const unsigned laneA = ((unsigned)((lmat & 1)*8 + lrow))*(LDH*2) + (unsigned)(lmat >> 1)*16;
    // B x4: m0=(nf0,klo) m1=(nf0,khi) m2=(nf1,klo) m3=(nf1,khi)
    const unsigned laneB = ((unsigned)((lmat >> 1)*8 + lrow))*(LDH*2) + (unsigned)(lmat & 1)*16;

    auto issue = [&](int kt, __half* as, __half* bs) {
        #pragma unroll
        for (int u = 0; u < 4; u++) {
            int idx = tid + u*256;               // 1024 x 16B for A
            int r = idx >> 3, c8 = idx & 7;
            cp16(&as[r*LDH + c8*8], &A[(size_t)(m0 + r)*768 + kt + c8*8]);
        }
        #pragma unroll
        for (int u = 0; u < 4; u++) {
            int idx = tid + u*256;
            int r = idx >> 3, c8 = idx & 7;
            cp16(&bs[r*LDH + c8*8], &W[(size_t)(n0 + r)*768 + kt + c8*8]);
        }
        CP_COMMIT();
    };

    issue(0, hA0, hB0);
    issue(64, hA1, hB1);
    if (tid < 128) sBias[tid] = bias[n0 + tid];

    const unsigned sA0 = (unsigned)__cvta_generic_to_shared(hA0);
    const unsigned sA1 = (unsigned)__cvta_generic_to_shared(hA1);
    const unsigned sB0 = (unsigned)__cvta_generic_to_shared(hB0);
    const unsigned sB1 = (unsigned)__cvta_generic_to_shared(hB1);

    float c[2][8][4];
    #pragma unroll
    for (int mf = 0; mf < 2; mf++)
        #pragma unroll
        for (int nf = 0; nf < 8; nf++)
            #pragma unroll
            for (int e = 0; e < 4; e++) c[mf][nf][e] = 0.0f;

    for (int it = 0; it < 12; it++) {
        CP_WAIT1();
        __syncthreads();
        const unsigned as_s = (it & 1) ? sA1 : sA0;
        const unsigned bs_s = (it & 1) ? sB1 : sB0;

        #pragma unroll
        for (int kc = 0; kc < 4; kc++) {
            unsigned a[2][4];
            #pragma unroll
            for (int mf = 0; mf < 2; mf++)
                ldsm4(a[mf][0], a[mf][1], a[mf][2], a[mf][3],
                      as_s + laneA + (unsigned)(((wm*32 + mf*16)*LDH + kc*16)*2));
            #pragma unroll
            for (int nfp = 0; nfp < 4; nfp++) {
                unsigned b0a, b1a, b0b, b1b;
                ldsm4(b0a, b1a, b0b, b1b,
                      bs_s + laneB + (unsigned)(((wn*64 + nfp*16)*LDH + kc*16)*2));
                mma16(c[0][2*nfp],   a[0], b0a, b1a);
                mma16(c[1][2*nfp],   a[1], b0a, b1a);
                mma16(c[0][2*nfp+1], a[0], b0b, b1b);
                mma16(c[1][2*nfp+1], a[1], b0b, b1b);
            }
        }
        __syncthreads();
        if (it + 2 < 12) issue((it + 2)*64, (it & 1) ? hA1 : hA0, (it & 1) ? hB1 : hB0);
        else CP_COMMIT();
    }

    // epilogue: direct stores, known fragment layout
    #pragma unroll
    for (int mf = 0; mf < 2; mf++) {
        #pragma unroll
        for (int nf = 0; nf < 8; nf++) {
            int m = m0 + wm*32 + mf*16 + g;       // rows m and m+8 (same 1024-block)
            int n = n0 + wn*64 + nf*8 + 2*t;
            float bv0 = sBias[n - n0], bv1 = sBias[n - n0 + 1];
            float v00 = c[mf][nf][0] + bv0, v01 = c[mf][nf][1] + bv1;   // row m
            float v10 = c[mf][nf][2] + bv0, v11 = c[mf][nf][3] + bv1;   // row m+8
            if (mode == 1) {
                *(float2*)&Cout[(size_t)m*768 + n]     = make_float2(v00, v01);
                *(float2*)&Cout[(size_t)(m+8)*768 + n] = make_float2(v10, v11);
            } else {
                int c3 = n / 768;
                int rem = n - c3*768;
                int h = rem >> 6, d = rem & 63;
                __half* dst = (c3 == 0) ? g_qh : (c3 == 1) ? g_kh : g_vh;
                int bb = m >> 10, tt = m & 1023;
                size_t rowbase = ((size_t)(bb*NHEAD + h)*SEQ + tt)*64 + d;
                *(__half2*)&dst[rowbase]        = __floats2half2_rn(v00, v01);
                *(__half2*)&dst[rowbase + 8*64] = __floats2half2_rn(v10, v11);
            }
        }
    }
}

// ---------------------------------------------------------------------------
// Flash attention with relative-position bias, fp16 mma.m16n8k16 + ldmatrix.
// grid (16 q-tiles, 48 bh), 128 threads = 4 warps, warp owns 16 q-rows.
// K fragments: ldmatrix.x4; V^T fragments: ldmatrix.x4.trans (no scalar packs).
// ---------------------------------------------------------------------------
#define LDKH 72
#define CSC 0.18033688f   // 0.125 * log2(e)

__global__ __launch_bounds__(128, 3) void attn_flash(const float* __restrict__ rel_emb)
{
    extern __shared__ __align__(16) char saraw[];
    __half* sK0 = (__half*)saraw;               // 64 x 72 halves
    __half* sK1 = sK0 + 64*LDKH;
    __half* sV0 = sK1 + 64*LDKH;
    __half* sV1 = sV0 + 64*LDKH;
    float*  sR  = (float*)(sV1 + 64*LDKH);      // 64 x 36 floats

    const int t0 = blockIdx.x * 64;
    const int bh = blockIdx.y;
    const int tid = threadIdx.x;
    const int w = tid >> 5;
    const int lane = tid & 31;
    const int g = lane >> 2;
    const int t = lane & 3;

    const __half* qb = g_qh + ((size_t)bh*SEQ + t0)*64;
    const __half* kb = g_kh + (size_t)bh*SEQ*64;
    const __half* vb = g_vh + (size_t)bh*SEQ*64;

    // ldmatrix lane address components (bytes)
    const int lmat = lane >> 3, lrow = lane & 7;
    // K (non-trans): m0=(nf0,klo) m1=(nf0,khi) m2=(nf1,klo) m3=(nf1,khi)
    const unsigned laneK = ((unsigned)((lmat >> 1)*8 + lrow))*(LDKH*2) + (unsigned)(lmat & 1)*16;
    // V (trans): m0=(klo,dn0) m1=(khi,dn0) m2=(klo,dn1) m3=(khi,dn1)
    const unsigned laneV = ((unsigned)((lmat & 1)*8 + lrow))*(LDKH*2) + (unsigned)(lmat >> 1)*16;
    // Q/A (non-trans): m0=(rows+0,klo) m1=(rows+8,klo) m2=(rows+0,khi) m3=(rows+8,khi)
    const unsigned laneQ = ((unsigned)((lmat & 1)*8 + lrow))*(LDKH*2) + (unsigned)(lmat >> 1)*16;

    auto issueKV = [&](int s0, __half* dK, __half* dV) {
        #pragma unroll
        for (int u = 0; u < 4; u++) {
            int idx = tid + u*128;               // 512 x 16B per matrix
            int r = idx >> 3, c8 = idx & 7;
            cp16(&dK[r*LDKH + c8*8], &kb[(size_t)(s0 + r)*64 + c8*8]);
            cp16(&dV[r*LDKH + c8*8], &vb[(size_t)(s0 + r)*64 + c8*8]);
        }
        CP_COMMIT();
    };

    issueKV(0, sK0, sV0);                          // group: stage 0
    // Q (half) -> sK1 ; rel_emb (fp32, 8448 B) -> sV1 region
    float* relbuf = (float*)sV1;
    #pragma unroll
    for (int u = 0; u < 4; u++) {
        int idx = tid + u*128;
        int r = idx >> 3, c8 = idx & 7;
        cp16(&sK1[r*LDKH + c8*8], &qb[(size_t)r*64 + c8*8]);
    }
    for (int idx = tid; idx < 33*16; idx += 128)
        cp16(&relbuf[idx*4], &rel_emb[(size_t)idx*4]);
    CP_COMMIT();
    CP_WAIT0();
    __syncthreads();

    // rel projections: sR[r][j] = (Q[r] . rel[j]) * scale * log2e
    for (int idx = tid; idx < 64*33; idx += 128) {
        int r = idx / 33, j = idx - r*33;
        const __half2* qr = (const __half2*)&sK1[r*LDKH];
        const float* rp = &relbuf[j*64];
        float acc = 0.0f;
        #pragma unroll 8
        for (int d = 0; d < 32; d++) {
            float2 qf = __half22float2(qr[d]);
            acc += qf.x*rp[2*d] + qf.y*rp[2*d+1];
        }
        sR[r*36 + j] = acc * CSC;
    }

    // persistent Q A-fragments via ldmatrix
    const int r0 = w*16 + g;           // this thread's q row (second = r0+8)
    unsigned qa[4][4];
    {
        unsigned q_s = (unsigned)__cvta_generic_to_shared(sK1);
        #pragma unroll
        for (int kc = 0; kc < 4; kc++)
            ldsm4(qa[kc][0], qa[kc][1], qa[kc][2], qa[kc][3],
                  q_s + laneQ + (unsigned)((w*16*LDKH + kc*16)*2));
    }
    __syncthreads();                 // sR ready; sK1/sV1 free
    issueKV(64, sK1, sV1);           // stage 1

    const unsigned cK0 = (unsigned)__cvta_generic_to_shared(sK0);
    const unsigned cK1 = (unsigned)__cvta_generic_to_shared(sK1);
    const unsigned cV0 = (unsigned)__cvta_generic_to_shared(sV0);
    const unsigned cV1 = (unsigned)__cvta_generic_to_shared(sV1);

    float o[8][4];
    #pragma unroll
    for (int i = 0; i < 8; i++)
        #pragma unroll
        for (int j = 0; j < 4; j++) o[i][j] = 0.0f;
    float m0v = -INFINITY, m1v = -INFINITY, l0 = 0.0f, l1 = 0.0f;

    const int rowt0 = t0 + r0, rowt1 = rowt0 + 8;

    for (int it = 0; it < 16; it++) {
        if (it == 15) CP_WAIT0(); else CP_WAIT1();
        __syncthreads();
        const unsigned kx = (it & 1) ? cK1 : cK0;
        const unsigned vx = (it & 1) ? cV1 : cV0;
        const int s0 = it * 64;

        // S = Q @ K^T   (16 x 64 per warp), K fragments via ldmatrix.x4
        float s[8][4];
        #pragma unroll
        for (int nfp = 0; nfp < 4; nfp++) {
            s[2*nfp][0] = s[2*nfp][1] = s[2*nfp][2] = s[2*nfp][3] = 0.0f;
            s[2*nfp+1][0] = s[2*nfp+1][1] = s[2*nfp+1][2] = s[2*nfp+1][3] = 0.0f;
            #pragma unroll
            for (int kc = 0; kc < 4; kc++) {
                unsigned b0a, b1a, b0b, b1b;
                ldsm4(b0a, b1a, b0b, b1b,
                      kx + laneK + (unsigned)((nfp*16*LDKH + kc*16)*2));
                mma16(s[2*nfp],   qa[kc], b0a, b1a);
                mma16(s[2*nfp+1], qa[kc], b0b, b1b);
            }
        }

        // bias + scale (log2 domain), row maxes
        const bool uni = (s0 >= t0 + 128) || (s0 + 128 <= t0);
        float bc0 = 0.0f, bc1 = 0.0f;
        if (uni) {
            int jj = (s0 > t0) ? 32 : 0;
            bc0 = sR[r0*36 + jj];
            bc1 = sR[(r0+8)*36 + jj];
        }
        float mn0 = -INFINITY, mn1 = -INFINITY;
        #pragma unroll
        for (int nf = 0; nf < 8; nf++) {
            int cc = s0 + nf*8 + 2*t;
            if (uni) {
                s[nf][0] = s[nf][0]*CSC + bc0;
                s[nf][1] = s[nf][1]*CSC + bc0;
                s[nf][2] = s[nf][2]*CSC + bc1;
                s[nf][3] = s[nf][3]*CSC + bc1;
            } else {
                int d00 = cc - rowt0;     d00 = d00 < -16 ? -16 : (d00 > 16 ? 16 : d00);
                int d01 = cc + 1 - rowt0; d01 = d01 < -16 ? -16 : (d01 > 16 ? 16 : d01);
                int d10 = cc - rowt1;     d10 = d10 < -16 ? -16 : (d10 > 16 ? 16 : d10);
                int d11 = cc + 1 - rowt1; d11 = d11 < -16 ? -16 : (d11 > 16 ? 16 : d11);
                s[nf][0] = s[nf][0]*CSC + sR[r0*36 + d00 + 16];
                s[nf][1] = s[nf][1]*CSC + sR[r0*36 + d01 + 16];
                s[nf][2] = s[nf][2]*CSC + sR[(r0+8)*36 + d10 + 16];
                s[nf][3] = s[nf][3]*CSC + sR[(r0+8)*36 + d11 + 16];
            }
            mn0 = fmaxf(mn0, fmaxf(s[nf][0], s[nf][1]));
            mn1 = fmaxf(mn1, fmaxf(s[nf][2], s[nf][3]));
        }
        mn0 = fmaxf(mn0, __shfl_xor_sync(0xffffffffu, mn0, 1));
        mn0 = fmaxf(mn0, __shfl_xor_sync(0xffffffffu, mn0, 2));
        mn1 = fmaxf(mn1, __shfl_xor_sync(0xffffffffu, mn1, 1));
        mn1 = fmaxf(mn1, __shfl_xor_sync(0xffffffffu, mn1, 2));
        float m0n = fmaxf(m0v, mn0);
        float m1n = fmaxf(m1v, mn1);
        float a0 = ex2(m0v - m0n);
        float a1 = ex2(m1v - m1n);
        m0v = m0n; m1v = m1n;

        // P = exp2(val - m); pack straight into f16 A-operand layout (no shuffles)
        float ls0 = 0.0f, ls1 = 0.0f;
        unsigned ph[8][2];
        #pragma unroll
        for (int nf = 0; nf < 8; nf++) {
            float p00 = ex2(s[nf][0] - m0n);
            float p01 = ex2(s[nf][1] - m0n);
            float p10 = ex2(s[nf][2] - m1n);
            float p11 = ex2(s[nf][3] - m1n);
            ls0 += p00 + p01;
            ls1 += p10 + p11;
            ph[nf][0] = h2u(__floats2half2_rn(p00, p01));  // row g
            ph[nf][1] = h2u(__floats2half2_rn(p10, p11));  // row g+8
        }
        ls0 += __shfl_xor_sync(0xffffffffu, ls0, 1);
        ls0 += __shfl_xor_sync(0xffffffffu, ls0, 2);
        ls1 += __shfl_xor_sync(0xffffffffu, ls1, 1);
        ls1 += __shfl_xor_sync(0xffffffffu, ls1, 2);
        l0 = l0*a0 + ls0;
        l1 = l1*a1 + ls1;
        #pragma unroll
        for (int dn = 0; dn < 8; dn++) {
            o[dn][0] *= a0; o[dn][1] *= a0;
            o[dn][2] *= a1; o[dn][3] *= a1;
        }

        // O += P @ V   (16 x 64); V^T fragments via ldmatrix.x4.trans
        #pragma unroll
        for (int kc = 0; kc < 4; kc++) {
            unsigned a[4] = { ph[2*kc][0], ph[2*kc][1], ph[2*kc+1][0], ph[2*kc+1][1] };
            #pragma unroll
            for (int dnp = 0; dnp < 4; dnp++) {
                unsigned b0a, b1a, b0b, b1b;
                ldsm4t(b0a, b1a, b0b, b1b,
                       vx + laneV + (unsigned)((kc*16*LDKH + dnp*16)*2));
                mma16(o[2*dnp],   a, b0a, b1a);
                mma16(o[2*dnp+1], a, b0b, b1b);
            }
        }
        __syncthreads();
        if (it + 2 < 16) issueKV((it + 2)*64, (it & 1) ? sK1 : sK0, (it & 1) ? sV1 : sV0);
        else CP_COMMIT();
    }

    // epilogue: normalize, write half [B,T,H*64]
    const int bb = bh / NHEAD, h = bh - bb*NHEAD;
    const float inv0 = 1.0f / l0;
    const float inv1 = 1.0f / l1;
    __half* o0 = g_attnh + ((size_t)(bb*SEQ + t0 + r0))*D_MODEL + h*64;
    __half* o1 = o0 + (size_t)8*D_MODEL;
    #pragma unroll
    for (int dn = 0; dn < 8; dn++) {
        *(__half2*)(o0 + dn*8 + 2*t) = __floats2half2_rn(o[dn][0]*inv0, o[dn][1]*inv0);
        *(__half2*)(o1 + dn*8 + 2*t) = __floats2half2_rn(o[dn][2]*inv1, o[dn][3]*inv1);
    }
}

// ---------------------------------------------------------------------------
extern "C" void kernel_launch(void* const* d_in, const int* in_sizes, int n_in,
                              void* d_out, int out_size)
{
    const float* x     = (const float*)d_in[0];
    const float* qkv_w = (const float*)d_in[1];
    const float* qkv_b = (const float*)d_in[2];
    const float* out_w = (const float*)d_in[3];
    const float* out_b = (const float*)d_in[4];
    const float* rel   = (const float*)d_in[5];
    float* out = (float*)d_out;

    (void)in_sizes; (void)n_in; (void)out_size;

    const int gemm_smem = (4*128*LDH)*2 + 128*4;                  // 74,240 B
    const int attn_smem = (4*64*LDKH)*2 + 64*36*4;                // 46,080 B
    cudaFuncSetAttribute(gemm_half, cudaFuncAttributeMaxDynamicSharedMemorySize, gemm_smem);
    cudaFuncSetAttribute(attn_flash, cudaFuncAttributeMaxDynamicSharedMemorySize, attn_smem);

    // 0) fp32 -> fp16 conversion pre-pass
    to_half<<<(MTOT*D_MODEL/4 + 255)/256, 256>>>(x, 0, MTOT*D_MODEL/4);
    to_half<<<(3*D_MODEL*D_MODEL/4 + 255)/256, 256>>>(qkv_w, 1, 3*D_MODEL*D_MODEL/4);
    to_half<<<(D_MODEL*D_MODEL/4 + 255)/256, 256>>>(out_w, 2, D_MODEL*D_MODEL/4);
    // 1) QKV projection -> half q/k/v [B,H,T,64]
    gemm_half<<<dim3(18, 32), 256, gemm_smem>>>(qkv_b, nullptr, 0);
    // 2) fused flash attention with relative-position bias
    attn_flash<<<dim3(16, 48), 128, attn_smem>>>(rel);
    // 3) output projection
    gemm_half<<<dim3(6, 32), 256, gemm_smem>>>(out_b, out, 1);
}

// round 10
// speedup vs baseline: 4.6272x; 1.4354x over previous
#include <cuda_runtime.h>
#include <cuda_fp16.h>
#include <math.h>

#define D_MODEL 768
#define NHEAD 12
#define HEAD_DIM 64
#define BATCH 4
#define SEQ 1024
#define MTOT (BATCH*SEQ)

// scratch (allocation-free requirement -> device globals)
__device__ __half g_xh[MTOT*D_MODEL];
__device__ __half g_wqkvh[3*D_MODEL*D_MODEL];
__device__ __half g_wouth[D_MODEL*D_MODEL];
__device__ __half g_qh[BATCH*NHEAD*SEQ*HEAD_DIM];
__device__ __half g_kh[BATCH*NHEAD*SEQ*HEAD_DIM];
__device__ __half g_vh[BATCH*NHEAD*SEQ*HEAD_DIM];
__device__ __half g_attnh[MTOT*D_MODEL];

// ---------------------------------------------------------------------------
// helpers
// ---------------------------------------------------------------------------
__device__ __forceinline__ void cp16(void* s, const void* g) {
    unsigned sa = (unsigned)__cvta_generic_to_shared(s);
    asm volatile("cp.async.cg.shared.global [%0], [%1], 16;" :: "r"(sa), "l"(g));
}
#define CP_COMMIT() asm volatile("cp.async.commit_group;")
#define CP_WAIT1()  asm volatile("cp.async.wait_group 1;")
#define CP_WAIT0()  asm volatile("cp.async.wait_group 0;")

__device__ __forceinline__ float ex2(float x) {
    float r;
    asm("ex2.approx.ftz.f32 %0, %1;" : "=f"(r) : "f"(x));
    return r;
}

// bit-cast __half2 -> u32 (register reinterpret, no instruction)
__device__ __forceinline__ unsigned h2u(__half2 h) {
    __half2_raw hr = *(__half2_raw*)&h;
    unsigned u = (unsigned)hr.x | ((unsigned)hr.y << 16);
    return u;
}

// warp-collective 8x8 b16 matrix loads (4 matrices per call)
__device__ __forceinline__ void ldsm4(unsigned& r0, unsigned& r1, unsigned& r2,
                                      unsigned& r3, unsigned addr) {
    asm volatile("ldmatrix.sync.aligned.m8n8.x4.shared.b16 {%0,%1,%2,%3}, [%4];"
                 : "=r"(r0), "=r"(r1), "=r"(r2), "=r"(r3) : "r"(addr));
}
__device__ __forceinline__ void ldsm4t(unsigned& r0, unsigned& r1, unsigned& r2,
                                       unsigned& r3, unsigned addr) {
    asm volatile("ldmatrix.sync.aligned.m8n8.x4.trans.shared.b16 {%0,%1,%2,%3}, [%4];"
                 : "=r"(r0), "=r"(r1), "=r"(r2), "=r"(r3) : "r"(addr));
}

// mma.m16n8k16 f16 inputs, f32 accum. Documented fragment layouts:
// A: a0=(row g, k=2t,2t+1) a1=(g+8, same) a2=(g, k+8) a3=(g+8, k+8)   [half2]
// B: b0=(k=2t,2t+1, col g) b1=(k=2t+8,+9, col g)
// C: c0=(g,2t) c1=(g,2t+1) c2=(g+8,2t) c3=(g+8,2t+1)
__device__ __forceinline__ void mma16(float* d, const unsigned* a, unsigned b0, unsigned b1) {
    asm volatile(
        "mma.sync.aligned.m16n8k16.row.col.f32.f16.f16.f32 "
        "{%0,%1,%2,%3}, {%4,%5,%6,%7}, {%8,%9}, {%0,%1,%2,%3};"
        : "+f"(d[0]), "+f"(d[1]), "+f"(d[2]), "+f"(d[3])
        : "r"(a[0]), "r"(a[1]), "r"(a[2]), "r"(a[3]), "r"(b0), "r"(b1));
}

// ---------------------------------------------------------------------------
// fp32 -> fp16 conversion pre-pass (which: 0=x, 1=qkv_w, 2=out_w)
// ---------------------------------------------------------------------------
__global__ void to_half(const float* __restrict__ src, int which, int n4)
{
    __half* dst = (which == 0) ? g_xh : (which == 1) ? g_wqkvh : g_wouth;
    int i = blockIdx.x * blockDim.x + threadIdx.x;
    if (i < n4) {
        float4 v = ((const float4*)src)[i];
        __half2* d2 = (__half2*)dst;
        d2[i*2]   = __floats2half2_rn(v.x, v.y);
        d2[i*2+1] = __floats2half2_rn(v.z, v.w);
    }
}

// ---------------------------------------------------------------------------
// fp16 GEMM: C[m,n] = sum_k A[m,k]*W[n,k] + bias[n]
// Block 128x128, K-chunk 64, cp.async double-buffered, 256 thr (8 warps),
// warp tile 32x64, all operand fetches via ldmatrix.x4.
// mode 0: A = g_xh,    epilogue -> half, scattered into g_qh/g_kh/g_vh [B,H,T,64]
// mode 1: A = g_attnh, epilogue -> f32 Cout row-major [4096,768]
// ---------------------------------------------------------------------------
#define LDH 72
__global__ __launch_bounds__(256, 2) void gemm_half(
    const float* __restrict__ bias,
    float* __restrict__ Cout,
    int mode)
{
    extern __shared__ __align__(16) char smraw[];
    __half* hA0 = (__half*)smraw;                 // 128 x 72 halves
    __half* hA1 = hA0 + 128*LDH;
    __half* hB0 = hA1 + 128*LDH;
    __half* hB1 = hB0 + 128*LDH;
    float*  sBias = (float*)(hB1 + 128*LDH);      // 128 floats

    const __half* A = (mode == 0) ? g_xh : g_attnh;
    const __half* W = (mode == 0) ? g_wqkvh : g_wouth;

    const int n0 = blockIdx.x * 128;
    const int m0 = blockIdx.y * 128;
    const int tid = threadIdx.x;
    const int warp = tid >> 5;
    const int lane = tid & 31;
    const int g = lane >> 2;
    const int t = lane & 3;
    const int wm = warp & 3;   // 4 m-slabs of 32
    const int wn = warp >> 2;  // 2 n-slabs of 64

    // ldmatrix lane address components (bytes)
    const int lmat = lane >> 3, lrow = lane & 7;
    // A x4: m0=(rows+0,klo) m1=(rows+8,klo) m2=(rows+0,khi) m3=(rows+8,khi)
    const unsigned laneA = ((unsigned)((lmat & 1)*8 + lrow))*(LDH*2) + (unsigned)(lmat >> 1)*16;
    // B x4: m0=(nf0,klo) m1=(nf0,khi) m2=(nf1,klo) m3=(nf1,khi)
    const unsigned laneB = ((unsigned)((lmat >> 1)*8 + lrow))*(LDH*2) + (unsigned)(lmat & 1)*16;

    auto issue = [&](int kt, __half* as, __half* bs) {
        #pragma unroll
        for (int u = 0; u < 4; u++) {
            int idx = tid + u*256;               // 1024 x 16B for A
            int r = idx >> 3, c8 = idx & 7;
            cp16(&as[r*LDH + c8*8], &A[(size_t)(m0 + r)*768 + kt + c8*8]);
        }
        #pragma unroll
        for (int u = 0; u < 4; u++) {
            int idx = tid + u*256;
            int r = idx >> 3, c8 = idx & 7;
            cp16(&bs[r*LDH + c8*8], &W[(size_t)(n0 + r)*768 + kt + c8*8]);
        }
        CP_COMMIT();
    };

    issue(0, hA0, hB0);
    issue(64, hA1, hB1);
    if (tid < 128) sBias[tid] = bias[n0 + tid];

    const unsigned sA0 = (unsigned)__cvta_generic_to_shared(hA0);
    const unsigned sA1 = (unsigned)__cvta_generic_to_shared(hA1);
    const unsigned sB0 = (unsigned)__cvta_generic_to_shared(hB0);
    const unsigned sB1 = (unsigned)__cvta_generic_to_shared(hB1);

    float c[2][8][4];
    #pragma unroll
    for (int mf = 0; mf < 2; mf++)
        #pragma unroll
        for (int nf = 0; nf < 8; nf++)
            #pragma unroll
            for (int e = 0; e < 4; e++) c[mf][nf][e] = 0.0f;

    for (int it = 0; it < 12; it++) {
        CP_WAIT1();
        __syncthreads();
        const unsigned as_s = (it & 1) ? sA1 : sA0;
        const unsigned bs_s = (it & 1) ? sB1 : sB0;

        #pragma unroll
        for (int kc = 0; kc < 4; kc++) {
            unsigned a[2][4];
            #pragma unroll
            for (int mf = 0; mf < 2; mf++)
                ldsm4(a[mf][0], a[mf][1], a[mf][2], a[mf][3],
                      as_s + laneA + (unsigned)(((wm*32 + mf*16)*LDH + kc*16)*2));
            #pragma unroll
            for (int nfp = 0; nfp < 4; nfp++) {
                unsigned b0a, b1a, b0b, b1b;
                ldsm4(b0a, b1a, b0b, b1b,
                      bs_s + laneB + (unsigned)(((wn*64 + nfp*16)*LDH + kc*16)*2));
                mma16(c[0][2*nfp],   a[0], b0a, b1a);
                mma16(c[1][2*nfp],   a[1], b0a, b1a);
                mma16(c[0][2*nfp+1], a[0], b0b, b1b);
                mma16(c[1][2*nfp+1], a[1], b0b, b1b);
            }
        }
        __syncthreads();
        if (it + 2 < 12) issue((it + 2)*64, (it & 1) ? hA1 : hA0, (it & 1) ? hB1 : hB0);
        else CP_COMMIT();
    }

    // epilogue: direct stores, known fragment layout
    #pragma unroll
    for (int mf = 0; mf < 2; mf++) {
        #pragma unroll
        for (int nf = 0; nf < 8; nf++) {
            int m = m0 + wm*32 + mf*16 + g;       // rows m and m+8 (same 1024-block)
            int n = n0 + wn*64 + nf*8 + 2*t;
            float bv0 = sBias[n - n0], bv1 = sBias[n - n0 + 1];
            float v00 = c[mf][nf][0] + bv0, v01 = c[mf][nf][1] + bv1;   // row m
            float v10 = c[mf][nf][2] + bv0, v11 = c[mf][nf][3] + bv1;   // row m+8
            if (mode == 1) {
                *(float2*)&Cout[(size_t)m*768 + n]     = make_float2(v00, v01);
                *(float2*)&Cout[(size_t)(m+8)*768 + n] = make_float2(v10, v11);
            } else {
                int c3 = n / 768;
                int rem = n - c3*768;
                int h = rem >> 6, d = rem & 63;
                __half* dst = (c3 == 0) ? g_qh : (c3 == 1) ? g_kh : g_vh;
                int bb = m >> 10, tt = m & 1023;
                size_t rowbase = ((size_t)(bb*NHEAD + h)*SEQ + tt)*64 + d;
                *(__half2*)&dst[rowbase]        = __floats2half2_rn(v00, v01);
                *(__half2*)&dst[rowbase + 8*64] = __floats2half2_rn(v10, v11);
            }
        }
    }
}

// ---------------------------------------------------------------------------
// Flash attention with relative-position bias, fp16 mma.m16n8k16 + ldmatrix.
// grid (16 q-tiles, 48 bh), 128 threads = 4 warps, warp owns 16 q-rows.
// rel table stored TRANSPOSED in smem (relT[d][j], stride 36) so the
// rel-projection dot products are bank-conflict-free (was 32-way conflicted).
// ---------------------------------------------------------------------------
#define LDKH 72
#define CSC 0.18033688f   // 0.125 * log2(e)

__global__ __launch_bounds__(128, 3) void attn_flash(const float* __restrict__ rel_emb)
{
    extern __shared__ __align__(16) char saraw[];
    __half* sK0 = (__half*)saraw;               // 64 x 72 halves
    __half* sK1 = sK0 + 64*LDKH;
    __half* sV0 = sK1 + 64*LDKH;
    __half* sV1 = sV0 + 64*LDKH;
    float*  sR  = (float*)(sV1 + 64*LDKH);      // 64 x 36 floats

    const int t0 = blockIdx.x * 64;
    const int bh = blockIdx.y;
    const int tid = threadIdx.x;
    const int w = tid >> 5;
    const int lane = tid & 31;
    const int g = lane >> 2;
    const int t = lane & 3;

    const __half* qb = g_qh + ((size_t)bh*SEQ + t0)*64;
    const __half* kb = g_kh + (size_t)bh*SEQ*64;
    const __half* vb = g_vh + (size_t)bh*SEQ*64;

    // ldmatrix lane address components (bytes)
    const int lmat = lane >> 3, lrow = lane & 7;
    // K (non-trans): m0=(nf0,klo) m1=(nf0,khi) m2=(nf1,klo) m3=(nf1,khi)
    const unsigned laneK = ((unsigned)((lmat >> 1)*8 + lrow))*(LDKH*2) + (unsigned)(lmat & 1)*16;
    // V (trans): m0=(klo,dn0) m1=(khi,dn0) m2=(klo,dn1) m3=(khi,dn1)
    const unsigned laneV = ((unsigned)((lmat & 1)*8 + lrow))*(LDKH*2) + (unsigned)(lmat >> 1)*16;
    // Q/A (non-trans): m0=(rows+0,klo) m1=(rows+8,klo) m2=(rows+0,khi) m3=(rows+8,khi)
    const unsigned laneQ = ((unsigned)((lmat & 1)*8 + lrow))*(LDKH*2) + (unsigned)(lmat >> 1)*16;

    auto issueKV = [&](int s0, __half* dK, __half* dV) {
        #pragma unroll
        for (int u = 0; u < 4; u++) {
            int idx = tid + u*128;               // 512 x 16B per matrix
            int r = idx >> 3, c8 = idx & 7;
            cp16(&dK[r*LDKH + c8*8], &kb[(size_t)(s0 + r)*64 + c8*8]);
            cp16(&dV[r*LDKH + c8*8], &vb[(size_t)(s0 + r)*64 + c8*8]);
        }
        CP_COMMIT();
    };

    issueKV(0, sK0, sV0);                          // group 1: KV stage 0
    // Q (half) -> sK1 via cp.async (group 2)
    #pragma unroll
    for (int u = 0; u < 4; u++) {
        int idx = tid + u*128;
        int r = idx >> 3, c8 = idx & 7;
        cp16(&sK1[r*LDKH + c8*8], &qb[(size_t)r*64 + c8*8]);
    }
    CP_COMMIT();
    // rel table -> sV1 region TRANSPOSED: relT[d*36 + j] (direct global loads).
    // Global reads coalesced (consecutive idx); smem writes 4-way, one-time.
    float* relT = (float*)sV1;                   // 64 x 36 floats = 9216 B
    for (int idx = tid; idx < 33*64; idx += 128) {
        int j = idx >> 6, d = idx & 63;
        relT[d*36 + j] = rel_emb[idx];
    }
    CP_WAIT0();
    __syncthreads();

    // rel projections: sR[r][j] = (Q[r] . rel[j]) * scale * log2e
    // relT reads: lanes hold distinct j at same d -> banks (4d+j)%32 distinct.
    for (int idx = tid; idx < 64*33; idx += 128) {
        int r = idx / 33, j = idx - r*33;
        const __half* qr = &sK1[r*LDKH];
        float acc = 0.0f;
        #pragma unroll 16
        for (int d = 0; d < 64; d++)
            acc += __half2float(qr[d]) * relT[d*36 + j];
        sR[r*36 + j] = acc * CSC;
    }

    // persistent Q A-fragments via ldmatrix
    const int r0 = w*16 + g;           // this thread's q row (second = r0+8)
    unsigned qa[4][4];
    {
        unsigned q_s = (unsigned)__cvta_generic_to_shared(sK1);
        #pragma unroll
        for (int kc = 0; kc < 4; kc++)
            ldsm4(qa[kc][0], qa[kc][1], qa[kc][2], qa[kc][3],
                  q_s + laneQ + (unsigned)((w*16*LDKH + kc*16)*2));
    }
    __syncthreads();                 // sR ready; sK1/sV1 free
    issueKV(64, sK1, sV1);           // group 3: KV stage 1

    const unsigned cK0 = (unsigned)__cvta_generic_to_shared(sK0);
    const unsigned cK1 = (unsigned)__cvta_generic_to_shared(sK1);
    const unsigned cV0 = (unsigned)__cvta_generic_to_shared(sV0);
    const unsigned cV1 = (unsigned)__cvta_generic_to_shared(sV1);

    float o[8][4];
    #pragma unroll
    for (int i = 0; i < 8; i++)
        #pragma unroll
        for (int j = 0; j < 4; j++) o[i][j] = 0.0f;
    float m0v = -INFINITY, m1v = -INFINITY, l0 = 0.0f, l1 = 0.0f;

    const int rowt0 = t0 + r0, rowt1 = rowt0 + 8;

    for (int it = 0; it < 16; it++) {
        if (it == 15) CP_WAIT0(); else CP_WAIT1();
        __syncthreads();
        const unsigned kx = (it & 1) ? cK1 : cK0;
        const unsigned vx = (it & 1) ? cV1 : cV0;
        const int s0 = it * 64;

        // S = Q @ K^T   (16 x 64 per warp), K fragments via ldmatrix.x4
        float s[8][4];
        #pragma unroll
        for (int nfp = 0; nfp < 4; nfp++) {
            s[2*nfp][0] = s[2*nfp][1] = s[2*nfp][2] = s[2*nfp][3] = 0.0f;
            s[2*nfp+1][0] = s[2*nfp+1][1] = s[2*nfp+1][2] = s[2*nfp+1][3] = 0.0f;
            #pragma unroll
            for (int kc = 0; kc < 4; kc++) {
                unsigned b0a, b1a, b0b, b1b;
                ldsm4(b0a, b1a, b0b, b1b,
                      kx + laneK + (unsigned)((nfp*16*LDKH + kc*16)*2));
                mma16(s[2*nfp],   qa[kc], b0a, b1a);
                mma16(s[2*nfp+1], qa[kc], b0b, b1b);
            }
        }

        // bias + scale (log2 domain), row maxes
        const bool uni = (s0 >= t0 + 128) || (s0 + 128 <= t0);
        float bc0 = 0.0f, bc1 = 0.0f;
        if (uni) {
            int jj = (s0 > t0) ? 32 : 0;
            bc0 = sR[r0*36 + jj];
            bc1 = sR[(r0+8)*36 + jj];
        }
        float mn0 = -INFINITY, mn1 = -INFINITY;
        #pragma unroll
        for (int nf = 0; nf < 8; nf++) {
            int cc = s0 + nf*8 + 2*t;
            if (uni) {
                s[nf][0] = s[nf][0]*CSC + bc0;
                s[nf][1] = s[nf][1]*CSC + bc0;
                s[nf][2] = s[nf][2]*CSC + bc1;
                s[nf][3] = s[nf][3]*CSC + bc1;
            } else {
                int d00 = cc - rowt0;     d00 = d00 < -16 ? -16 : (d00 > 16 ? 16 : d00);
                int d01 = cc + 1 - rowt0; d01 = d01 < -16 ? -16 : (d01 > 16 ? 16 : d01);
                int d10 = cc - rowt1;     d10 = d10 < -16 ? -16 : (d10 > 16 ? 16 : d10);
                int d11 = cc + 1 - rowt1; d11 = d11 < -16 ? -16 : (d11 > 16 ? 16 : d11);
                s[nf][0] = s[nf][0]*CSC + sR[r0*36 + d00 + 16];
                s[nf][1] = s[nf][1]*CSC + sR[r0*36 + d01 + 16];
                s[nf][2] = s[nf][2]*CSC + sR[(r0+8)*36 + d10 + 16];
                s[nf][3] = s[nf][3]*CSC + sR[(r0+8)*36 + d11 + 16];
            }
            mn0 = fmaxf(mn0, fmaxf(s[nf][0], s[nf][1]));
            mn1 = fmaxf(mn1, fmaxf(s[nf][2], s[nf][3]));
        }
        mn0 = fmaxf(mn0, __shfl_xor_sync(0xffffffffu, mn0, 1));
        mn0 = fmaxf(mn0, __shfl_xor_sync(0xffffffffu, mn0, 2));
        mn1 = fmaxf(mn1, __shfl_xor_sync(0xffffffffu, mn1, 1));
        mn1 = fmaxf(mn1, __shfl_xor_sync(0xffffffffu, mn1, 2));
        float m0n = fmaxf(m0v, mn0);
        float m1n = fmaxf(m1v, mn1);
        float a0 = ex2(m0v - m0n);
        float a1 = ex2(m1v - m1n);
        m0v = m0n; m1v = m1n;

        // P = exp2(val - m); pack straight into f16 A-operand layout (no shuffles)
        float ls0 = 0.0f, ls1 = 0.0f;
        unsigned ph[8][2];
        #pragma unroll
        for (int nf = 0; nf < 8; nf++) {
            float p00 = ex2(s[nf][0] - m0n);
            float p01 = ex2(s[nf][1] - m0n);
            float p10 = ex2(s[nf][2] - m1n);
            float p11 = ex2(s[nf][3] - m1n);
            ls0 += p00 + p01;
            ls1 += p10 + p11;
            ph[nf][0] = h2u(__floats2half2_rn(p00, p01));  // row g
            ph[nf][1] = h2u(__floats2half2_rn(p10, p11));  // row g+8
        }
        ls0 += __shfl_xor_sync(0xffffffffu, ls0, 1);
        ls0 += __shfl_xor_sync(0xffffffffu, ls0, 2);
        ls1 += __shfl_xor_sync(0xffffffffu, ls1, 1);
        ls1 += __shfl_xor_sync(0xffffffffu, ls1, 2);
        l0 = l0*a0 + ls0;
        l1 = l1*a1 + ls1;
        #pragma unroll
        for (int dn = 0; dn < 8; dn++) {
            o[dn][0] *= a0; o[dn][1] *= a0;
            o[dn][2] *= a1; o[dn][3] *= a1;
        }

        // O += P @ V   (16 x 64); V^T fragments via ldmatrix.x4.trans
        #pragma unroll
        for (int kc = 0; kc < 4; kc++) {
            unsigned a[4] = { ph[2*kc][0], ph[2*kc][1], ph[2*kc+1][0], ph[2*kc+1][1] };
            #pragma unroll
            for (int dnp = 0; dnp < 4; dnp++) {
                unsigned b0a, b1a, b0b, b1b;
                ldsm4t(b0a, b1a, b0b, b1b,
                       vx + laneV + (unsigned)((kc*16*LDKH + dnp*16)*2));
                mma16(o[2*dnp],   a, b0a, b1a);
                mma16(o[2*dnp+1], a, b0b, b1b);
            }
        }
        __syncthreads();
        if (it + 2 < 16) issueKV((it + 2)*64, (it & 1) ? sK1 : sK0, (it & 1) ? sV1 : sV0);
        else CP_COMMIT();
    }

    // epilogue: normalize, write half [B,T,H*64]
    const int bb = bh / NHEAD, h = bh - bb*NHEAD;
    const float inv0 = 1.0f / l0;
    const float inv1 = 1.0f / l1;
    __half* o0 = g_attnh + ((size_t)(bb*SEQ + t0 + r0))*D_MODEL + h*64;
    __half* o1 = o0 + (size_t)8*D_MODEL;
    #pragma unroll
    for (int dn = 0; dn < 8; dn++) {
        *(__half2*)(o0 + dn*8 + 2*t) = __floats2half2_rn(o[dn][0]*inv0, o[dn][1]*inv0);
        *(__half2*)(o1 + dn*8 + 2*t) = __floats2half2_rn(o[dn][2]*inv1, o[dn][3]*inv1);
    }
}

// ---------------------------------------------------------------------------
extern "C" void kernel_launch(void* const* d_in, const int* in_sizes, int n_in,
                              void* d_out, int out_size)
{
    const float* x     = (const float*)d_in[0];
    const float* qkv_w = (const float*)d_in[1];
    const float* qkv_b = (const float*)d_in[2];
    const float* out_w = (const float*)d_in[3];
    const float* out_b = (const float*)d_in[4];
    const float* rel   = (const float*)d_in[5];
    float* out = (float*)d_out;

    (void)in_sizes; (void)n_in; (void)out_size;

    const int gemm_smem = (4*128*LDH)*2 + 128*4;                  // 74,240 B
    const int attn_smem = (4*64*LDKH)*2 + 64*36*4;                // 46,080 B
    cudaFuncSetAttribute(gemm_half, cudaFuncAttributeMaxDynamicSharedMemorySize, gemm_smem);
    cudaFuncSetAttribute(attn_flash, cudaFuncAttributeMaxDynamicSharedMemorySize, attn_smem);

    // 0) fp32 -> fp16 conversion pre-pass
    to_half<<<(MTOT*D_MODEL/4 + 255)/256, 256>>>(x, 0, MTOT*D_MODEL/4);
    to_half<<<(3*D_MODEL*D_MODEL/4 + 255)/256, 256>>>(qkv_w, 1, 3*D_MODEL*D_MODEL/4);
    to_half<<<(D_MODEL*D_MODEL/4 + 255)/256, 256>>>(out_w, 2, D_MODEL*D_MODEL/4);
    // 1) QKV projection -> half q/k/v [B,H,T,64]
    gemm_half<<<dim3(18, 32), 256, gemm_smem>>>(qkv_b, nullptr, 0);
    // 2) fused flash attention with relative-position bias
    attn_flash<<<dim3(16, 48), 128, attn_smem>>>(rel);
    // 3) output projection
    gemm_half<<<dim3(6, 32), 256, gemm_smem>>>(out_b, out, 1);
}

// round 11
// speedup vs baseline: 4.7961x; 1.0365x over previous
#include <cuda_runtime.h>
#include <cuda_fp16.h>
#include <math.h>

#define D_MODEL 768
#define NHEAD 12
#define HEAD_DIM 64
#define BATCH 4
#define SEQ 1024
#define MTOT (BATCH*SEQ)

// scratch (allocation-free requirement -> device globals)
__device__ __half g_xh[MTOT*D_MODEL];
__device__ __half g_wqkvh[3*D_MODEL*D_MODEL];
__device__ __half g_wouth[D_MODEL*D_MODEL];
__device__ __half g_qh[BATCH*NHEAD*SEQ*HEAD_DIM];
__device__ __half g_kh[BATCH*NHEAD*SEQ*HEAD_DIM];
__device__ __half g_vh[BATCH*NHEAD*SEQ*HEAD_DIM];
__device__ __half g_attnh[MTOT*D_MODEL];

// ---------------------------------------------------------------------------
// helpers
// ---------------------------------------------------------------------------
__device__ __forceinline__ void cp16(void* s, const void* g) {
    unsigned sa = (unsigned)__cvta_generic_to_shared(s);
    asm volatile("cp.async.cg.shared.global [%0], [%1], 16;" :: "r"(sa), "l"(g));
}
#define CP_COMMIT() asm volatile("cp.async.commit_group;")
#define CP_WAIT1()  asm volatile("cp.async.wait_group 1;")
#define CP_WAIT0()  asm volatile("cp.async.wait_group 0;")

__device__ __forceinline__ float ex2(float x) {
    float r;
    asm("ex2.approx.ftz.f32 %0, %1;" : "=f"(r) : "f"(x));
    return r;
}

// bit-cast __half2 -> u32 (register reinterpret, no instruction)
__device__ __forceinline__ unsigned h2u(__half2 h) {
    __half2_raw hr = *(__half2_raw*)&h;
    unsigned u = (unsigned)hr.x | ((unsigned)hr.y << 16);
    return u;
}

// warp-collective 8x8 b16 matrix loads (4 matrices per call)
__device__ __forceinline__ void ldsm4(unsigned& r0, unsigned& r1, unsigned& r2,
                                      unsigned& r3, unsigned addr) {
    asm volatile("ldmatrix.sync.aligned.m8n8.x4.shared.b16 {%0,%1,%2,%3}, [%4];"
                 : "=r"(r0), "=r"(r1), "=r"(r2), "=r"(r3) : "r"(addr));
}
__device__ __forceinline__ void ldsm4t(unsigned& r0, unsigned& r1, unsigned& r2,
                                       unsigned& r3, unsigned addr) {
    asm volatile("ldmatrix.sync.aligned.m8n8.x4.trans.shared.b16 {%0,%1,%2,%3}, [%4];"
                 : "=r"(r0), "=r"(r1), "=r"(r2), "=r"(r3) : "r"(addr));
}

// mma.m16n8k16 f16 inputs, f32 accum (documented fragment layouts)
__device__ __forceinline__ void mma16(float* d, const unsigned* a, unsigned b0, unsigned b1) {
    asm volatile(
        "mma.sync.aligned.m16n8k16.row.col.f32.f16.f16.f32 "
        "{%0,%1,%2,%3}, {%4,%5,%6,%7}, {%8,%9}, {%0,%1,%2,%3};"
        : "+f"(d[0]), "+f"(d[1]), "+f"(d[2]), "+f"(d[3])
        : "r"(a[0]), "r"(a[1]), "r"(a[2]), "r"(a[3]), "r"(b0), "r"(b1));
}

// ---------------------------------------------------------------------------
// fp32 -> fp16 conversion pre-pass (which: 0=x, 1=qkv_w, 2=out_w)
// ---------------------------------------------------------------------------
__global__ void to_half(const float* __restrict__ src, int which, int n4)
{
    __half* dst = (which == 0) ? g_xh : (which == 1) ? g_wqkvh : g_wouth;
    int i = blockIdx.x * blockDim.x + threadIdx.x;
    if (i < n4) {
        float4 v = ((const float4*)src)[i];
        __half2* d2 = (__half2*)dst;
        d2[i*2]   = __floats2half2_rn(v.x, v.y);
        d2[i*2+1] = __floats2half2_rn(v.z, v.w);
    }
}

// ---------------------------------------------------------------------------
// fp16 GEMM: C[m,n] = sum_k A[m,k]*W[n,k] + bias[n]
// Block 128x128, K-chunk 64, 3-stage cp.async pipeline (ONE sync per iter),
// 256 thr (8 warps), warp tile 32x64, operands via ldmatrix.x4.
// mode 0: A = g_xh,    epilogue -> half, scattered into g_qh/g_kh/g_vh [B,H,T,64]
// mode 1: A = g_attnh, epilogue -> f32 Cout row-major [4096,768]
// ---------------------------------------------------------------------------
#define LDH 72
#define GST (2*128*LDH)   // halves per stage (A tile + B tile)
__global__ __launch_bounds__(256, 2) void gemm_half(
    const float* __restrict__ bias,
    float* __restrict__ Cout,
    int mode)
{
    extern __shared__ __align__(16) char smraw[];
    __half* st = (__half*)smraw;                  // 3 stages x (A 128x72 | B 128x72)
    float*  sBias = (float*)(st + 3*GST);         // 128 floats

    const __half* A = (mode == 0) ? g_xh : g_attnh;
    const __half* W = (mode == 0) ? g_wqkvh : g_wouth;

    const int n0 = blockIdx.x * 128;
    const int m0 = blockIdx.y * 128;
    const int tid = threadIdx.x;
    const int warp = tid >> 5;
    const int lane = tid & 31;
    const int g = lane >> 2;
    const int t = lane & 3;
    const int wm = warp & 3;   // 4 m-slabs of 32
    const int wn = warp >> 2;  // 2 n-slabs of 64

    // ldmatrix lane address components (bytes)
    const int lmat = lane >> 3, lrow = lane & 7;
    const unsigned laneA = ((unsigned)((lmat & 1)*8 + lrow))*(LDH*2) + (unsigned)(lmat >> 1)*16;
    const unsigned laneB = ((unsigned)((lmat >> 1)*8 + lrow))*(LDH*2) + (unsigned)(lmat & 1)*16;

    auto issue = [&](int kt, int s) {
        __half* as = st + s*GST;
        __half* bs = as + 128*LDH;
        #pragma unroll
        for (int u = 0; u < 4; u++) {
            int idx = tid + u*256;               // 1024 x 16B for A
            int r = idx >> 3, c8 = idx & 7;
            cp16(&as[r*LDH + c8*8], &A[(size_t)(m0 + r)*768 + kt + c8*8]);
        }
        #pragma unroll
        for (int u = 0; u < 4; u++) {
            int idx = tid + u*256;
            int r = idx >> 3, c8 = idx & 7;
            cp16(&bs[r*LDH + c8*8], &W[(size_t)(n0 + r)*768 + kt + c8*8]);
        }
        CP_COMMIT();
    };

    issue(0, 0);
    issue(64, 1);
    if (tid < 128) sBias[tid] = bias[n0 + tid];

    const unsigned stBase = (unsigned)__cvta_generic_to_shared(st);

    float c[2][8][4];
    #pragma unroll
    for (int mf = 0; mf < 2; mf++)
        #pragma unroll
        for (int nf = 0; nf < 8; nf++)
            #pragma unroll
            for (int e = 0; e < 4; e++) c[mf][nf][e] = 0.0f;

    for (int it = 0; it < 12; it++) {
        CP_WAIT1();                 // stage it resident (pending <= 1 newer)
        __syncthreads();            // all warps done with compute(it-1)
        if (it + 2 < 12) issue((it + 2)*64, (it + 2) % 3);   // overwrites buf (it-1)%3: safe
        else CP_COMMIT();           // keep 1-commit-per-iter accounting

        const unsigned as_s = stBase + (unsigned)((it % 3)*GST*2);
        const unsigned bs_s = as_s + 128*LDH*2;

        #pragma unroll
        for (int kc = 0; kc < 4; kc++) {
            unsigned a[2][4];
            #pragma unroll
            for (int mf = 0; mf < 2; mf++)
                ldsm4(a[mf][0], a[mf][1], a[mf][2], a[mf][3],
                      as_s + laneA + (unsigned)(((wm*32 + mf*16)*LDH + kc*16)*2));
            #pragma unroll
            for (int nfp = 0; nfp < 4; nfp++) {
                unsigned b0a, b1a, b0b, b1b;
                ldsm4(b0a, b1a, b0b, b1b,
                      bs_s + laneB + (unsigned)(((wn*64 + nfp*16)*LDH + kc*16)*2));
                mma16(c[0][2*nfp],   a[0], b0a, b1a);
                mma16(c[1][2*nfp],   a[1], b0a, b1a);
                mma16(c[0][2*nfp+1], a[0], b0b, b1b);
                mma16(c[1][2*nfp+1], a[1], b0b, b1b);
            }
        }
    }

    // epilogue: direct stores, known fragment layout
    #pragma unroll
    for (int mf = 0; mf < 2; mf++) {
        #pragma unroll
        for (int nf = 0; nf < 8; nf++) {
            int m = m0 + wm*32 + mf*16 + g;       // rows m and m+8 (same 1024-block)
            int n = n0 + wn*64 + nf*8 + 2*t;
            float bv0 = sBias[n - n0], bv1 = sBias[n - n0 + 1];
            float v00 = c[mf][nf][0] + bv0, v01 = c[mf][nf][1] + bv1;   // row m
            float v10 = c[mf][nf][2] + bv0, v11 = c[mf][nf][3] + bv1;   // row m+8
            if (mode == 1) {
                *(float2*)&Cout[(size_t)m*768 + n]     = make_float2(v00, v01);
                *(float2*)&Cout[(size_t)(m+8)*768 + n] = make_float2(v10, v11);
            } else {
                int c3 = n / 768;
                int rem = n - c3*768;
                int h = rem >> 6, d = rem & 63;
                __half* dst = (c3 == 0) ? g_qh : (c3 == 1) ? g_kh : g_vh;
                int bb = m >> 10, tt = m & 1023;
                size_t rowbase = ((size_t)(bb*NHEAD + h)*SEQ + tt)*64 + d;
                *(__half2*)&dst[rowbase]        = __floats2half2_rn(v00, v01);
                *(__half2*)&dst[rowbase + 8*64] = __floats2half2_rn(v10, v11);
            }
        }
    }
}

// ---------------------------------------------------------------------------
// Flash attention with relative-position bias, fp16 mma.m16n8k16 + ldmatrix.
// grid (8 q-tiles, 48 bh), 256 threads = 8 warps, Q tile 128 rows
// (warp w owns rows w*16..w*16+15; per-warp hot loop identical to R10).
// rel table transposed in smem (conflict-free); K/V traffic halved per q-row.
// ---------------------------------------------------------------------------
#define LDKH 72
#define CSC 0.18033688f   // 0.125 * log2(e)

__global__ __launch_bounds__(256, 2) void attn_flash(const float* __restrict__ rel_emb)
{
    extern __shared__ __align__(16) char saraw[];
    __half* sK0 = (__half*)saraw;               // 64 x 72 halves
    __half* sK1 = sK0 + 64*LDKH;
    __half* sV0 = sK1 + 64*LDKH;
    __half* sV1 = sV0 + 64*LDKH;
    __half* sQ  = sV1 + 64*LDKH;                // 128 x 72 halves (prologue stage)
    float*  sR  = (float*)(sQ + 128*LDKH);      // 128 x 36 floats

    const int t0 = blockIdx.x * 128;
    const int bh = blockIdx.y;
    const int tid = threadIdx.x;
    const int w = tid >> 5;            // 0..7
    const int lane = tid & 31;
    const int g = lane >> 2;
    const int t = lane & 3;

    const __half* qb = g_qh + ((size_t)bh*SEQ + t0)*64;
    const __half* kb = g_kh + (size_t)bh*SEQ*64;
    const __half* vb = g_vh + (size_t)bh*SEQ*64;

    // ldmatrix lane address components (bytes)
    const int lmat = lane >> 3, lrow = lane & 7;
    const unsigned laneK = ((unsigned)((lmat >> 1)*8 + lrow))*(LDKH*2) + (unsigned)(lmat & 1)*16;
    const unsigned laneV = ((unsigned)((lmat & 1)*8 + lrow))*(LDKH*2) + (unsigned)(lmat >> 1)*16;
    const unsigned laneQ = ((unsigned)((lmat & 1)*8 + lrow))*(LDKH*2) + (unsigned)(lmat >> 1)*16;

    auto issueKV = [&](int s0, __half* dK, __half* dV) {
        #pragma unroll
        for (int u = 0; u < 2; u++) {
            int idx = tid + u*256;               // 512 x 16B per matrix
            int r = idx >> 3, c8 = idx & 7;
            cp16(&dK[r*LDKH + c8*8], &kb[(size_t)(s0 + r)*64 + c8*8]);
            cp16(&dV[r*LDKH + c8*8], &vb[(size_t)(s0 + r)*64 + c8*8]);
        }
        CP_COMMIT();
    };

    issueKV(0, sK0, sV0);                          // group 1: KV stage 0
    // Q (128 rows, half) -> sQ via cp.async (group 2)
    #pragma unroll
    for (int u = 0; u < 4; u++) {
        int idx = tid + u*256;                     // 1024 x 16B
        int r = idx >> 3, c8 = idx & 7;
        cp16(&sQ[r*LDKH + c8*8], &qb[(size_t)r*64 + c8*8]);
    }
    CP_COMMIT();
    // rel table -> sV1 region TRANSPOSED: relT[d*36 + j] (direct global loads)
    float* relT = (float*)sV1;                     // 64 x 36 floats = 9216 B
    for (int idx = tid; idx < 33*64; idx += 256) {
        int j = idx >> 6, d = idx & 63;
        relT[d*36 + j] = rel_emb[idx];
    }
    CP_WAIT0();
    __syncthreads();

    // rel projections: sR[r][j] = (Q[r] . rel[j]) * scale * log2e  (conflict-free)
    for (int idx = tid; idx < 128*33; idx += 256) {
        int r = idx / 33, j = idx - r*33;
        const __half* qr = &sQ[r*LDKH];
        float acc = 0.0f;
        #pragma unroll 16
        for (int d = 0; d < 64; d++)
            acc += __half2float(qr[d]) * relT[d*36 + j];
        sR[r*36 + j] = acc * CSC;
    }

    // persistent Q A-fragments via ldmatrix (warp w: rows w*16..w*16+15)
    const int r0 = w*16 + g;
    unsigned qa[4][4];
    {
        unsigned q_s = (unsigned)__cvta_generic_to_shared(sQ);
        #pragma unroll
        for (int kc = 0; kc < 4; kc++)
            ldsm4(qa[kc][0], qa[kc][1], qa[kc][2], qa[kc][3],
                  q_s + laneQ + (unsigned)((w*16*LDKH + kc*16)*2));
    }
    __syncthreads();                 // sR ready; sV1 (relT) free
    issueKV(64, sK1, sV1);           // group 3: KV stage 1

    const unsigned cK0 = (unsigned)__cvta_generic_to_shared(sK0);
    const unsigned cK1 = (unsigned)__cvta_generic_to_shared(sK1);
    const unsigned cV0 = (unsigned)__cvta_generic_to_shared(sV0);
    const unsigned cV1 = (unsigned)__cvta_generic_to_shared(sV1);

    float o[8][4];
    #pragma unroll
    for (int i = 0; i < 8; i++)
        #pragma unroll
        for (int j = 0; j < 4; j++) o[i][j] = 0.0f;
    float m0v = -INFINITY, m1v = -INFINITY, l0 = 0.0f, l1 = 0.0f;

    const int rowt0 = t0 + r0, rowt1 = rowt0 + 8;

    for (int it = 0; it < 16; it++) {
        if (it == 15) CP_WAIT0(); else CP_WAIT1();
        __syncthreads();
        const unsigned kx = (it & 1) ? cK1 : cK0;
        const unsigned vx = (it & 1) ? cV1 : cV0;
        const int s0 = it * 64;

        // S = Q @ K^T   (16 x 64 per warp), K fragments via ldmatrix.x4
        float s[8][4];
        #pragma unroll
        for (int nfp = 0; nfp < 4; nfp++) {
            s[2*nfp][0] = s[2*nfp][1] = s[2*nfp][2] = s[2*nfp][3] = 0.0f;
            s[2*nfp+1][0] = s[2*nfp+1][1] = s[2*nfp+1][2] = s[2*nfp+1][3] = 0.0f;
            #pragma unroll
            for (int kc = 0; kc < 4; kc++) {
                unsigned b0a, b1a, b0b, b1b;
                ldsm4(b0a, b1a, b0b, b1b,
                      kx + laneK + (unsigned)((nfp*16*LDKH + kc*16)*2));
                mma16(s[2*nfp],   qa[kc], b0a, b1a);
                mma16(s[2*nfp+1], qa[kc], b0b, b1b);
            }
        }

        // bias + scale (log2 domain), row maxes
        // 128-row Q tile: uniform-bias margin re-derived (needs |dt|>=17 everywhere)
        const bool uni = (s0 >= t0 + 192) || (s0 + 128 <= t0);
        float bc0 = 0.0f, bc1 = 0.0f;
        if (uni) {
            int jj = (s0 > t0) ? 32 : 0;
            bc0 = sR[r0*36 + jj];
            bc1 = sR[(r0+8)*36 + jj];
        }
        float mn0 = -INFINITY, mn1 = -INFINITY;
        #pragma unroll
        for (int nf = 0; nf < 8; nf++) {
            int cc = s0 + nf*8 + 2*t;
            if (uni) {
                s[nf][0] = s[nf][0]*CSC + bc0;
                s[nf][1] = s[nf][1]*CSC + bc0;
                s[nf][2] = s[nf][2]*CSC + bc1;
                s[nf][3] = s[nf][3]*CSC + bc1;
            } else {
                int d00 = cc - rowt0;     d00 = d00 < -16 ? -16 : (d00 > 16 ? 16 : d00);
                int d01 = cc + 1 - rowt0; d01 = d01 < -16 ? -16 : (d01 > 16 ? 16 : d01);
                int d10 = cc - rowt1;     d10 = d10 < -16 ? -16 : (d10 > 16 ? 16 : d10);
                int d11 = cc + 1 - rowt1; d11 = d11 < -16 ? -16 : (d11 > 16 ? 16 : d11);
                s[nf][0] = s[nf][0]*CSC + sR[r0*36 + d00 + 16];
                s[nf][1] = s[nf][1]*CSC + sR[r0*36 + d01 + 16];
                s[nf][2] = s[nf][2]*CSC + sR[(r0+8)*36 + d10 + 16];
                s[nf][3] = s[nf][3]*CSC + sR[(r0+8)*36 + d11 + 16];
            }
            mn0 = fmaxf(mn0, fmaxf(s[nf][0], s[nf][1]));
            mn1 = fmaxf(mn1, fmaxf(s[nf][2], s[nf][3]));
        }
        mn0 = fmaxf(mn0, __shfl_xor_sync(0xffffffffu, mn0, 1));
        mn0 = fmaxf(mn0, __shfl_xor_sync(0xffffffffu, mn0, 2));
        mn1 = fmaxf(mn1, __shfl_xor_sync(0xffffffffu, mn1, 1));
        mn1 = fmaxf(mn1, __shfl_xor_sync(0xffffffffu, mn1, 2));
        float m0n = fmaxf(m0v, mn0);
        float m1n = fmaxf(m1v, mn1);
        float a0 = ex2(m0v - m0n);
        float a1 = ex2(m1v - m1n);
        m0v = m0n; m1v = m1n;

        // P = exp2(val - m); pack straight into f16 A-operand layout (no shuffles)
        float ls0 = 0.0f, ls1 = 0.0f;
        unsigned ph[8][2];
        #pragma unroll
        for (int nf = 0; nf < 8; nf++) {
            float p00 = ex2(s[nf][0] - m0n);
            float p01 = ex2(s[nf][1] - m0n);
            float p10 = ex2(s[nf][2] - m1n);
            float p11 = ex2(s[nf][3] - m1n);
            ls0 += p00 + p01;
            ls1 += p10 + p11;
            ph[nf][0] = h2u(__floats2half2_rn(p00, p01));  // row g
            ph[nf][1] = h2u(__floats2half2_rn(p10, p11));  // row g+8
        }
        ls0 += __shfl_xor_sync(0xffffffffu, ls0, 1);
        ls0 += __shfl_xor_sync(0xffffffffu, ls0, 2);
        ls1 += __shfl_xor_sync(0xffffffffu, ls1, 1);
        ls1 += __shfl_xor_sync(0xffffffffu, ls1, 2);
        l0 = l0*a0 + ls0;
        l1 = l1*a1 + ls1;
        #pragma unroll
        for (int dn = 0; dn < 8; dn++) {
            o[dn][0] *= a0; o[dn][1] *= a0;
            o[dn][2] *= a1; o[dn][3] *= a1;
        }

        // O += P @ V   (16 x 64); V^T fragments via ldmatrix.x4.trans
        #pragma unroll
        for (int kc = 0; kc < 4; kc++) {
            unsigned a[4] = { ph[2*kc][0], ph[2*kc][1], ph[2*kc+1][0], ph[2*kc+1][1] };
            #pragma unroll
            for (int dnp = 0; dnp < 4; dnp++) {
                unsigned b0a, b1a, b0b, b1b;
                ldsm4t(b0a, b1a, b0b, b1b,
                       vx + laneV + (unsigned)((kc*16*LDKH + dnp*16)*2));
                mma16(o[2*dnp],   a, b0a, b1a);
                mma16(o[2*dnp+1], a, b0b, b1b);
            }
        }
        __syncthreads();
        if (it + 2 < 16) issueKV((it + 2)*64, (it & 1) ? sK1 : sK0, (it & 1) ? sV1 : sV0);
        else CP_COMMIT();
    }

    // epilogue: normalize, write half [B,T,H*64]
    const int bb = bh / NHEAD, h = bh - bb*NHEAD;
    const float inv0 = 1.0f / l0;
    const float inv1 = 1.0f / l1;
    __half* o0 = g_attnh + ((size_t)(bb*SEQ + t0 + r0))*D_MODEL + h*64;
    __half* o1 = o0 + (size_t)8*D_MODEL;
    #pragma unroll
    for (int dn = 0; dn < 8; dn++) {
        *(__half2*)(o0 + dn*8 + 2*t) = __floats2half2_rn(o[dn][0]*inv0, o[dn][1]*inv0);
        *(__half2*)(o1 + dn*8 + 2*t) = __floats2half2_rn(o[dn][2]*inv1, o[dn][3]*inv1);
    }
}

// ---------------------------------------------------------------------------
extern "C" void kernel_launch(void* const* d_in, const int* in_sizes, int n_in,
                              void* d_out, int out_size)
{
    const float* x     = (const float*)d_in[0];
    const float* qkv_w = (const float*)d_in[1];
    const float* qkv_b = (const float*)d_in[2];
    const float* out_w = (const float*)d_in[3];
    const float* out_b = (const float*)d_in[4];
    const float* rel   = (const float*)d_in[5];
    float* out = (float*)d_out;

    (void)in_sizes; (void)n_in; (void)out_size;

    const int gemm_smem = 3*GST*2 + 128*4;                        // 111,104 B
    const int attn_smem = (4*64*LDKH + 128*LDKH)*2 + 128*36*4;    // 73,728 B
    cudaFuncSetAttribute(gemm_half, cudaFuncAttributeMaxDynamicSharedMemorySize, gemm_smem);
    cudaFuncSetAttribute(attn_flash, cudaFuncAttributeMaxDynamicSharedMemorySize, attn_smem);

    // 0) fp32 -> fp16 conversion pre-pass
    to_half<<<(MTOT*D_MODEL/4 + 255)/256, 256>>>(x, 0, MTOT*D_MODEL/4);
    to_half<<<(3*D_MODEL*D_MODEL/4 + 255)/256, 256>>>(qkv_w, 1, 3*D_MODEL*D_MODEL/4);
    to_half<<<(D_MODEL*D_MODEL/4 + 255)/256, 256>>>(out_w, 2, D_MODEL*D_MODEL/4);
    // 1) QKV projection -> half q/k/v [B,H,T,64]
    gemm_half<<<dim3(18, 32), 256, gemm_smem>>>(qkv_b, nullptr, 0);
    // 2) fused flash attention with relative-position bias (128-row Q tiles)
    attn_flash<<<dim3(8, 48), 256, attn_smem>>>(rel);
    // 3) output projection
    gemm_half<<<dim3(6, 32), 256, gemm_smem>>>(out_b, out, 1);
}